// round 9
// baseline (speedup 1.0000x reference)
#include <cuda_runtime.h>
#include <cuda_bf16.h>
#include <cstdint>

#define NROWS 8192
#define NDIM  128
#define NS    64

static constexpr float EXP_SCALE = 14.4269504088896340736f; // log2(e)/tau
static constexpr int NT = 64;                    // 128-row tiles per matrix
static constexpr int ITEMS_S12 = NT * NT;        // 4096
static constexpr int ITEMS_S11 = NT * (NT + 1) / 2;  // 2080
static constexpr int TOTAL_ITEMS = ITEMS_S12 + ITEMS_S11;

// ---------------- device scratch (bf16 operands) ----------------
__device__ __align__(256) __nv_bfloat16 g_a [NROWS * NDIM];  // n1 * log2(e)/tau
__device__ __align__(256) __nv_bfloat16 g_b1[NROWS * NDIM];  // n1
__device__ __align__(256) __nv_bfloat16 g_b2[NROWS * NDIM];  // n2
__device__ float g_d12[NROWS];
__device__ float g_d11[NROWS];
__device__ float g_adv[NROWS];
__device__ float g_rowsum[2][NROWS];
__device__ int   g_counter;

// ---------------- helpers ----------------
__device__ __forceinline__ uint32_t smem_u32(const void* p) {
    uint32_t a;
    asm("{ .reg .u64 t; cvta.to.shared.u64 t, %1; cvt.u32.u64 %0, t; }" : "=r"(a) : "l"(p));
    return a;
}
__device__ __forceinline__ float warp_sum(float v) {
#pragma unroll
    for (int o = 16; o > 0; o >>= 1) v += __shfl_xor_sync(0xFFFFFFFFu, v, o);
    return v;
}
__device__ __forceinline__ float ex2f(float x) {
    float y; asm("ex2.approx.f32 %0, %1;" : "=f"(y) : "f"(x)); return y;
}
__device__ __forceinline__ void ldsm_x4(uint32_t& r0, uint32_t& r1, uint32_t& r2, uint32_t& r3,
                                        uint32_t addr) {
    asm volatile("ldmatrix.sync.aligned.m8n8.x4.shared.b16 {%0,%1,%2,%3}, [%4];"
                 : "=r"(r0), "=r"(r1), "=r"(r2), "=r"(r3) : "r"(addr));
}
__device__ __forceinline__ void mma_bf16(float& c0, float& c1, float& c2, float& c3,
                                         uint32_t a0, uint32_t a1, uint32_t a2, uint32_t a3,
                                         uint32_t b0, uint32_t b1) {
    asm volatile(
        "mma.sync.aligned.m16n8k16.row.col.f32.bf16.bf16.f32 "
        "{%0,%1,%2,%3},{%4,%5,%6,%7},{%8,%9},{%0,%1,%2,%3};"
        : "+f"(c0), "+f"(c1), "+f"(c2), "+f"(c3)
        : "r"(a0), "r"(a1), "r"(a2), "r"(a3), "r"(b0), "r"(b1));
}

// bf16 tile: 128 rows x 256B, 16 chunks(16B)/row, chunk swizzle c ^= (row&7)
__device__ __forceinline__ uint32_t tile_addr(uint32_t base, uint32_t row, uint32_t chunk) {
    return base + row * 256u + ((chunk ^ (row & 7u)) << 4);
}
// 256 threads: queue one [128x128] bf16 tile (no commit)
__device__ __forceinline__ void load_tile(uint32_t dst, const __nv_bfloat16* src) {
    const char* s = (const char*)src;
    int t = threadIdx.x;
#pragma unroll
    for (int j = 0; j < 8; ++j) {
        uint32_t q = (uint32_t)t + 256u * j;
        uint32_t r = q >> 4, c = q & 15u;
        uint32_t d = tile_addr(dst, r, c);
        asm volatile("cp.async.cg.shared.global [%0], [%1], 16;"
                     :: "r"(d), "l"(s + ((size_t)r << 8) + ((size_t)c << 4)) : "memory");
    }
}
#define CP_COMMIT() asm volatile("cp.async.commit_group;" ::: "memory")
#define CP_WAIT(n)  asm volatile("cp.async.wait_group %0;" :: "n"(n) : "memory")

static constexpr int TILE_BYTES = 32768;
static constexpr int SMEM_DYN   = TILE_BYTES * 4;   // A0 A1 B0 B1

__device__ __forceinline__ int tri_base(int i) { return i * NT - (i * (i - 1)) / 2; }
__device__ __forceinline__ void decode_item(int idx, int& mat, int& ti, int& tj) {
    if (idx < ITEMS_S12) { mat = 0; ti = idx >> 6; tj = idx & 63; return; }
    mat = 1;
    int k = idx - ITEMS_S12;
    int i = (int)((129.0f - sqrtf(16641.0f - 8.0f * (float)k)) * 0.5f);
    if (i < 0) i = 0; if (i > 63) i = 63;
    while (i > 0 && tri_base(i) > k) --i;
    while (i < 63 && tri_base(i + 1) <= k) ++i;
    ti = i; tj = i + (k - tri_base(i));
}

// ---------------- kernel A: normalize + diagonals + adversarial + zeroing ----
__global__ void __launch_bounds__(256) prep_kernel(const float* __restrict__ z1,
                                                   const float* __restrict__ z2,
                                                   const float* __restrict__ cpre,
                                                   const float* __restrict__ lab) {
    int gtid = blockIdx.x * 256 + threadIdx.x;
    if (gtid < 2 * NROWS) ((float*)g_rowsum)[gtid] = 0.f;
    if (gtid == 0) g_counter = 0;

    int w = threadIdx.x >> 5, lane = threadIdx.x & 31;
    int row = blockIdx.x * 8 + w;
    float4 a = ((const float4*)(z1 + (size_t)row * NDIM))[lane];
    float4 b = ((const float4*)(z2 + (size_t)row * NDIM))[lane];
    float ss1 = warp_sum(a.x * a.x + a.y * a.y + a.z * a.z + a.w * a.w);
    float ss2 = warp_sum(b.x * b.x + b.y * b.y + b.z * b.z + b.w * b.w);
    float inv1 = 1.f / fmaxf(sqrtf(ss1), 1e-8f);
    float inv2 = 1.f / fmaxf(sqrtf(ss2), 1e-8f);
    float4 n1 = make_float4(a.x * inv1, a.y * inv1, a.z * inv1, a.w * inv1);
    float4 n2 = make_float4(b.x * inv2, b.y * inv2, b.z * inv2, b.w * inv2);
    float d12 = warp_sum(n1.x * n2.x + n1.y * n2.y + n1.z * n2.z + n1.w * n2.w);
    float d11 = warp_sum(n1.x * n1.x + n1.y * n1.y + n1.z * n1.z + n1.w * n1.w);

    __nv_bfloat162* pa = (__nv_bfloat162*)(g_a + (size_t)row * NDIM) + lane * 2;
    pa[0] = __floats2bfloat162_rn(n1.x * EXP_SCALE, n1.y * EXP_SCALE);
    pa[1] = __floats2bfloat162_rn(n1.z * EXP_SCALE, n1.w * EXP_SCALE);
    __nv_bfloat162* p1 = (__nv_bfloat162*)(g_b1 + (size_t)row * NDIM) + lane * 2;
    p1[0] = __floats2bfloat162_rn(n1.x, n1.y);
    p1[1] = __floats2bfloat162_rn(n1.z, n1.w);
    __nv_bfloat162* p2 = (__nv_bfloat162*)(g_b2 + (size_t)row * NDIM) + lane * 2;
    p2[0] = __floats2bfloat162_rn(n2.x, n2.y);
    p2[1] = __floats2bfloat162_rn(n2.z, n2.w);
    if (lane == 0) { g_d12[row] = d12; g_d11[row] = d11; }

    float2 cc = ((const float2*)(cpre + (size_t)row * NS))[lane];
    float2 ll = ((const float2*)(lab + (size_t)row * NS))[lane];
    float csum = warp_sum(cc.x * cc.x + cc.y * cc.y);
    float bv = ll.x; int bi = lane * 2; float bc = cc.x;
    if (ll.y > bv) { bv = ll.y; bi = lane * 2 + 1; bc = cc.y; }
#pragma unroll
    for (int o = 16; o > 0; o >>= 1) {
        float ov = __shfl_xor_sync(0xFFFFFFFFu, bv, o);
        int   oi = __shfl_xor_sync(0xFFFFFFFFu, bi, o);
        float oc = __shfl_xor_sync(0xFFFFFFFFu, bc, o);
        if (ov > bv || (ov == bv && oi < bi)) { bv = ov; bi = oi; bc = oc; }
    }
    if (lane == 0) {
        float picked = bc / fmaxf(sqrtf(csum), 1e-12f);
        g_adv[row] = -logf(1e-12f + 1.f - picked);
    }
}

// ---------------- kernel B: persistent work-queue sim-GEMM + exp sums ----------
// item = one 128x128 output tile. S12: all 64x64 pairs. S11: upper triangle only;
// off-diag items credit row sums to ti-rows and col sums to tj-rows (symmetry).
__global__ void __launch_bounds__(256, 1) sim_rowsum_kernel() {
    extern __shared__ char smem_raw[];
    __shared__ int s_next;
    const uint32_t base = smem_u32(smem_raw);
    const int tid = threadIdx.x, wid = tid >> 5, lane = tid & 31;
    const int m_base = (wid & 3) * 32;
    const int jslab  = wid >> 2;

    if (tid == 0) s_next = atomicAdd(&g_counter, 1);
    __syncthreads();
    int cur = s_next;
    if (cur >= TOTAL_ITEMS) return;
    int mat, ti, tj;
    decode_item(cur, mat, ti, tj);

    // prologue: load A(ti), B(tj) into buffer 0 as one group
    load_tile(base, g_a + (size_t)ti * 128 * NDIM);
    load_tile(base + 2 * TILE_BYTES, (mat ? g_b1 : g_b2) + (size_t)tj * 128 * NDIM);
    CP_COMMIT();
    if (tid == 0) s_next = atomicAdd(&g_counter, 1);
    int ab = 0, bb = 0, ati = ti;

    const uint32_t rA  = (uint32_t)(m_base + (lane & 15));
    const uint32_t gA  = (uint32_t)(lane >> 4);
    const uint32_t rB0 = (uint32_t)(jslab * 64 + (lane & 7) + ((lane >> 4) << 3));
    const uint32_t gB  = (uint32_t)((lane >> 3) & 1);

    for (;;) {
        __syncthreads();                       // prev compute done; s_next valid
        const int nid = s_next;
        __syncthreads();                       // everyone read s_next
        const bool has_next = nid < TOTAL_ITEMS;
        int nmat = 0, nti = 0, ntj = 0;
        bool a_chg = false;
        if (has_next) {
            decode_item(nid, nmat, nti, ntj);
            a_chg = (nti != ati);
            load_tile(base + (uint32_t)(2 + (1 - bb)) * TILE_BYTES,
                      (nmat ? g_b1 : g_b2) + (size_t)ntj * 128 * NDIM);
            if (a_chg)
                load_tile(base + (uint32_t)(1 - ab) * TILE_BYTES,
                          g_a + (size_t)nti * 128 * NDIM);
            CP_COMMIT();
            if (tid == 0) s_next = atomicAdd(&g_counter, 1);
        }
        if (has_next) { CP_WAIT(1); } else { CP_WAIT(0); }
        __syncthreads();                       // current buffers complete for all

        // ---- compute current item ----
        const uint32_t abase = base + (uint32_t)ab * TILE_BYTES;
        const uint32_t bbase = base + (uint32_t)(2 + bb) * TILE_BYTES;

        uint32_t af[2][8][4];
#pragma unroll
        for (int mb = 0; mb < 2; ++mb)
#pragma unroll
            for (int k = 0; k < 8; ++k) {
                uint32_t addr = tile_addr(abase, rA + mb * 16u, 2u * k + gA);
                ldsm_x4(af[mb][k][0], af[mb][k][1], af[mb][k][2], af[mb][k][3], addr);
            }

        float c[2][8][4];
#pragma unroll
        for (int mb = 0; mb < 2; ++mb)
#pragma unroll
            for (int n = 0; n < 8; ++n)
#pragma unroll
                for (int q = 0; q < 4; ++q) c[mb][n][q] = 0.f;

#pragma unroll
        for (int k = 0; k < 8; ++k) {
            uint32_t bf[4][4];
#pragma unroll
            for (int nb = 0; nb < 4; ++nb) {
                uint32_t addr = tile_addr(bbase, rB0 + nb * 16u, 2u * k + gB);
                ldsm_x4(bf[nb][0], bf[nb][1], bf[nb][2], bf[nb][3], addr);
            }
#pragma unroll
            for (int mb = 0; mb < 2; ++mb)
#pragma unroll
                for (int nb = 0; nb < 4; ++nb) {
                    mma_bf16(c[mb][nb * 2][0], c[mb][nb * 2][1],
                             c[mb][nb * 2][2], c[mb][nb * 2][3],
                             af[mb][k][0], af[mb][k][1], af[mb][k][2], af[mb][k][3],
                             bf[nb][0], bf[nb][1]);
                    mma_bf16(c[mb][nb * 2 + 1][0], c[mb][nb * 2 + 1][1],
                             c[mb][nb * 2 + 1][2], c[mb][nb * 2 + 1][3],
                             af[mb][k][0], af[mb][k][1], af[mb][k][2], af[mb][k][3],
                             bf[nb][2], bf[nb][3]);
                }
        }

        // ---- epilogue: exp + row sums (+ col sums for S11 off-diag) ----
        const bool do_col = (mat == 1) && (ti != tj);
        float s00 = 0.f, s01 = 0.f, s10 = 0.f, s11 = 0.f;
        float col0[8], col1[8];
#pragma unroll
        for (int n = 0; n < 8; ++n) {
            float e00 = ex2f(c[0][n][0]), e01 = ex2f(c[0][n][1]);
            float e02 = ex2f(c[0][n][2]), e03 = ex2f(c[0][n][3]);
            float e10 = ex2f(c[1][n][0]), e11 = ex2f(c[1][n][1]);
            float e12 = ex2f(c[1][n][2]), e13 = ex2f(c[1][n][3]);
            s00 += e00 + e01; s01 += e02 + e03;
            s10 += e10 + e11; s11 += e12 + e13;
            col0[n] = e00 + e02 + e10 + e12;   // col n*8 + (lane&3)*2
            col1[n] = e01 + e03 + e11 + e13;   // col n*8 + (lane&3)*2 + 1
        }
#pragma unroll
        for (int o = 1; o <= 2; o <<= 1) {
            s00 += __shfl_xor_sync(0xFFFFFFFFu, s00, o);
            s01 += __shfl_xor_sync(0xFFFFFFFFu, s01, o);
            s10 += __shfl_xor_sync(0xFFFFFFFFu, s10, o);
            s11 += __shfl_xor_sync(0xFFFFFFFFu, s11, o);
        }
        if ((lane & 3) == 0) {
            float* dst = &g_rowsum[mat][ti * 128 + m_base + (lane >> 2)];
            atomicAdd(dst,      s00);
            atomicAdd(dst + 8,  s01);
            atomicAdd(dst + 16, s10);
            atomicAdd(dst + 24, s11);
        }
        if (do_col) {
#pragma unroll
            for (int n = 0; n < 8; ++n)
#pragma unroll
                for (int o = 4; o <= 16; o <<= 1) {
                    col0[n] += __shfl_xor_sync(0xFFFFFFFFu, col0[n], o);
                    col1[n] += __shfl_xor_sync(0xFFFFFFFFu, col1[n], o);
                }
            if (lane < 4) {
                float* dst = &g_rowsum[1][tj * 128 + jslab * 64 + lane * 2];
#pragma unroll
                for (int n = 0; n < 8; ++n) {
                    atomicAdd(dst + n * 8,     col0[n]);
                    atomicAdd(dst + n * 8 + 1, col1[n]);
                }
            }
        }

        if (!has_next) break;
        mat = nmat; ti = nti; tj = ntj;
        bb ^= 1;
        if (a_chg) { ab ^= 1; ati = nti; }
    }
}

// ---------------- kernel C: final reduction ----------------
__global__ void __launch_bounds__(256) finish_kernel(float* __restrict__ out) {
    __shared__ float sc[256], sa[256];
    int tid = threadIdx.x;
    float c = 0.f, a = 0.f;
    for (int r = tid; r < NROWS; r += 256) {
        float num  = ex2f(EXP_SCALE * g_d12[r]);
        float diag = ex2f(EXP_SCALE * g_d11[r]);
        float den  = g_rowsum[0][r] + g_rowsum[1][r] - diag;
        c -= logf(1e-12f + num / den);
        a += g_adv[r];
    }
    sc[tid] = c; sa[tid] = a;
    __syncthreads();
    for (int st = 128; st > 0; st >>= 1) {
        if (tid < st) { sc[tid] += sc[tid + st]; sa[tid] += sa[tid + st]; }
        __syncthreads();
    }
    if (tid == 0)
        out[0] = sc[0] / (8192.0f * 16383.0f) + sa[0];
}

extern "C" void kernel_launch(void* const* d_in, const int* in_sizes, int n_in,
                              void* d_out, int out_size) {
    const float* z1  = (const float*)d_in[0];
    const float* z2  = (const float*)d_in[1];
    const float* c   = (const float*)d_in[2];
    const float* lab = (const float*)d_in[3];
    cudaFuncSetAttribute(sim_rowsum_kernel,
                         cudaFuncAttributeMaxDynamicSharedMemorySize, SMEM_DYN);
    prep_kernel<<<NROWS / 8, 256>>>(z1, z2, c, lab);
    sim_rowsum_kernel<<<148, 256, SMEM_DYN>>>();
    finish_kernel<<<1, 256>>>((float*)d_out);
}

// round 12
// speedup vs baseline: 1.1574x; 1.1574x over previous
#include <cuda_runtime.h>
#include <cuda_bf16.h>
#include <cstdint>

#define NROWS 8192
#define NDIM  128
#define NS    64

static constexpr float EXP_SCALE = 14.4269504088896340736f; // log2(e)/tau
static constexpr int NT = 64;
static constexpr int ITEMS_S12 = NT * NT;            // 4096
static constexpr int ITEMS_S11 = NT * (NT + 1) / 2;  // 2080
static constexpr int TOTAL_ITEMS = ITEMS_S12 + ITEMS_S11;  // 6176
static constexpr int NCTA = 148;

// ---------------- device scratch (bf16 operands) ----------------
__device__ __align__(256) __nv_bfloat16 g_a [NROWS * NDIM];  // n1 * log2(e)/tau
__device__ __align__(256) __nv_bfloat16 g_b1[NROWS * NDIM];  // n1
__device__ __align__(256) __nv_bfloat16 g_b2[NROWS * NDIM];  // n2
__device__ float g_d12[NROWS];
__device__ float g_d11[NROWS];
__device__ float g_adv[NROWS];
__device__ float g_rowsum[2][NROWS];

// ---------------- helpers ----------------
__device__ __forceinline__ uint32_t smem_u32(const void* p) {
    uint32_t a;
    asm("{ .reg .u64 t; cvta.to.shared.u64 t, %1; cvt.u32.u64 %0, t; }" : "=r"(a) : "l"(p));
    return a;
}
__device__ __forceinline__ float warp_sum(float v) {
#pragma unroll
    for (int o = 16; o > 0; o >>= 1) v += __shfl_xor_sync(0xFFFFFFFFu, v, o);
    return v;
}
__device__ __forceinline__ float ex2f(float x) {
    float y; asm("ex2.approx.f32 %0, %1;" : "=f"(y) : "f"(x)); return y;
}
__device__ __forceinline__ void ldsm_x4(uint32_t& r0, uint32_t& r1, uint32_t& r2, uint32_t& r3,
                                        uint32_t addr) {
    asm volatile("ldmatrix.sync.aligned.m8n8.x4.shared.b16 {%0,%1,%2,%3}, [%4];"
                 : "=r"(r0), "=r"(r1), "=r"(r2), "=r"(r3) : "r"(addr));
}
__device__ __forceinline__ void mma_bf16(float& c0, float& c1, float& c2, float& c3,
                                         uint32_t a0, uint32_t a1, uint32_t a2, uint32_t a3,
                                         uint32_t b0, uint32_t b1) {
    asm volatile(
        "mma.sync.aligned.m16n8k16.row.col.f32.bf16.bf16.f32 "
        "{%0,%1,%2,%3},{%4,%5,%6,%7},{%8,%9},{%0,%1,%2,%3};"
        : "+f"(c0), "+f"(c1), "+f"(c2), "+f"(c3)
        : "r"(a0), "r"(a1), "r"(a2), "r"(a3), "r"(b0), "r"(b1));
}
__device__ __forceinline__ void mbar_init(uint32_t a, uint32_t c) {
    asm volatile("mbarrier.init.shared.b64 [%0], %1;" :: "r"(a), "r"(c) : "memory");
}
__device__ __forceinline__ void mbar_wait(uint32_t a, uint32_t par) {
    asm volatile(
        "{\n\t.reg .pred P1;\n\t"
        "W_%=:\n\t"
        "mbarrier.try_wait.parity.acquire.cta.shared::cta.b64 P1, [%0], %1, 0x989680;\n\t"
        "@P1 bra.uni D_%=;\n\t"
        "bra.uni W_%=;\n\t"
        "D_%=:\n\t}"
        :: "r"(a), "r"(par) : "memory");
}
__device__ __forceinline__ void mbar_arrive(uint32_t a) {
    asm volatile("mbarrier.arrive.shared.b64 _, [%0];" :: "r"(a) : "memory");
}

// bf16 tile: 128 rows x 256B, 16 chunks(16B)/row, chunk swizzle c ^= (row&7)
__device__ __forceinline__ uint32_t tile_addr(uint32_t base, uint32_t row, uint32_t chunk) {
    return base + row * 256u + ((chunk ^ (row & 7u)) << 4);
}

static constexpr int TILE_BYTES   = 32768;
static constexpr int SMEM_BAR_OFF = 4 * TILE_BYTES;   // 4 B stages
static constexpr int SMEM_DYN     = SMEM_BAR_OFF + 128;

// global item ordering: [0,4096): S12 (ti=idx>>6, tj=idx&63);
// [4096,6176): S11 upper triangle row-major.
__device__ __forceinline__ int tri_base(int i) { return i * NT - (i * (i - 1)) / 2; }
__device__ __forceinline__ void decode_item(int idx, int& mat, int& ti, int& tj) {
    if (idx < ITEMS_S12) { mat = 0; ti = idx >> 6; tj = idx & 63; return; }
    mat = 1;
    int k = idx - ITEMS_S12;
    int i = (int)((129.0f - sqrtf(16641.0f - 8.0f * (float)k)) * 0.5f);
    if (i < 0) i = 0; if (i > 63) i = 63;
    while (i > 0 && tri_base(i) > k) --i;
    while (i < 63 && tri_base(i + 1) <= k) ++i;
    ti = i; tj = i + (k - tri_base(i));
}
__device__ __forceinline__ void step_item(int& m, int& i, int& j) {
    if (m == 0) { if (++j == 64) { j = 0; if (++i == 64) { m = 1; i = 0; j = 0; } } }
    else        { if (++j == 64) { ++i; j = i; } }
}

// ---------------- kernel A: normalize + diagonals + adversarial + zeroing ----
__global__ void __launch_bounds__(256) prep_kernel(const float* __restrict__ z1,
                                                   const float* __restrict__ z2,
                                                   const float* __restrict__ cpre,
                                                   const float* __restrict__ lab) {
    int gtid = blockIdx.x * 256 + threadIdx.x;
    if (gtid < 2 * NROWS) ((float*)g_rowsum)[gtid] = 0.f;

    int w = threadIdx.x >> 5, lane = threadIdx.x & 31;
    int row = blockIdx.x * 8 + w;
    float4 a = ((const float4*)(z1 + (size_t)row * NDIM))[lane];
    float4 b = ((const float4*)(z2 + (size_t)row * NDIM))[lane];
    float ss1 = warp_sum(a.x * a.x + a.y * a.y + a.z * a.z + a.w * a.w);
    float ss2 = warp_sum(b.x * b.x + b.y * b.y + b.z * b.z + b.w * b.w);
    float inv1 = 1.f / fmaxf(sqrtf(ss1), 1e-8f);
    float inv2 = 1.f / fmaxf(sqrtf(ss2), 1e-8f);
    float4 n1 = make_float4(a.x * inv1, a.y * inv1, a.z * inv1, a.w * inv1);
    float4 n2 = make_float4(b.x * inv2, b.y * inv2, b.z * inv2, b.w * inv2);
    float d12 = warp_sum(n1.x * n2.x + n1.y * n2.y + n1.z * n2.z + n1.w * n2.w);
    float d11 = warp_sum(n1.x * n1.x + n1.y * n1.y + n1.z * n1.z + n1.w * n1.w);

    __nv_bfloat162* pa = (__nv_bfloat162*)(g_a + (size_t)row * NDIM) + lane * 2;
    pa[0] = __floats2bfloat162_rn(n1.x * EXP_SCALE, n1.y * EXP_SCALE);
    pa[1] = __floats2bfloat162_rn(n1.z * EXP_SCALE, n1.w * EXP_SCALE);
    __nv_bfloat162* p1 = (__nv_bfloat162*)(g_b1 + (size_t)row * NDIM) + lane * 2;
    p1[0] = __floats2bfloat162_rn(n1.x, n1.y);
    p1[1] = __floats2bfloat162_rn(n1.z, n1.w);
    __nv_bfloat162* p2 = (__nv_bfloat162*)(g_b2 + (size_t)row * NDIM) + lane * 2;
    p2[0] = __floats2bfloat162_rn(n2.x, n2.y);
    p2[1] = __floats2bfloat162_rn(n2.z, n2.w);
    if (lane == 0) { g_d12[row] = d12; g_d11[row] = d11; }

    float2 cc = ((const float2*)(cpre + (size_t)row * NS))[lane];
    float2 ll = ((const float2*)(lab + (size_t)row * NS))[lane];
    float csum = warp_sum(cc.x * cc.x + cc.y * cc.y);
    float bv = ll.x; int bi = lane * 2; float bc = cc.x;
    if (ll.y > bv) { bv = ll.y; bi = lane * 2 + 1; bc = cc.y; }
#pragma unroll
    for (int o = 16; o > 0; o >>= 1) {
        float ov = __shfl_xor_sync(0xFFFFFFFFu, bv, o);
        int   oi = __shfl_xor_sync(0xFFFFFFFFu, bi, o);
        float oc = __shfl_xor_sync(0xFFFFFFFFu, bc, o);
        if (ov > bv || (ov == bv && oi < bi)) { bv = ov; bi = oi; bc = oc; }
    }
    if (lane == 0) {
        float picked = bc / fmaxf(sqrtf(csum), 1e-12f);
        g_adv[row] = -logf(1e-12f + 1.f - picked);
    }
}

// ---------------- kernel B: static-schedule warp-specialized sim + exp sums ----
// 148 CTAs x 320 threads (8 consumer warps + 2 producer warps).
// CTA b owns items [b*TOTAL/148, (b+1)*TOTAL/148). S11 upper-triangle items
// credit row sums to ti rows and col sums to tj rows (symmetry).
__global__ void __launch_bounds__(320, 1) sim_rowsum_kernel() {
    extern __shared__ char smem_raw[];
    const uint32_t base = smem_u32(smem_raw);
    const int tid = threadIdx.x, wid = tid >> 5, lane = tid & 31;
    const int k0 = (blockIdx.x * TOTAL_ITEMS) / NCTA;
    const int k1 = ((blockIdx.x + 1) * TOTAL_ITEMS) / NCTA;
    const int n_items = k1 - k0;

    if (tid == 0) {
#pragma unroll
        for (int s = 0; s < 4; ++s) {
            mbar_init(base + SMEM_BAR_OFF + s * 16, 64);      // full: 64 producer threads
            mbar_init(base + SMEM_BAR_OFF + s * 16 + 8, 8);   // empty: 8 consumer warps
        }
    }
    __syncthreads();

    int mat, ti, tj;
    decode_item(k0, mat, ti, tj);

    if (wid >= 8) {
        // ---------------- producers: stream B tiles ----------------
        const int pid = tid - 256;                 // 0..63
        int m = mat, i = ti, j = tj;
        for (int k = 0; k < n_items; ++k) {
            const int s = k & 3, w = k >> 2;
            mbar_wait(base + SMEM_BAR_OFF + s * 16 + 8, 1u ^ (uint32_t)(w & 1));
            const char* src = (const char*)((m ? g_b1 : g_b2) + (size_t)j * 128 * NDIM);
            const uint32_t stg = base + (uint32_t)s * TILE_BYTES;
#pragma unroll
            for (int jj = 0; jj < 32; ++jj) {
                uint32_t q = (uint32_t)pid + 64u * jj;
                uint32_t r = q >> 4, c = q & 15u;
                uint32_t d = tile_addr(stg, r, c);
                asm volatile("cp.async.cg.shared.global [%0], [%1], 16;"
                             :: "r"(d), "l"(src + ((size_t)r << 8) + ((size_t)c << 4)) : "memory");
            }
            asm volatile("cp.async.mbarrier.arrive.noinc.shared::cta.b64 [%0];"
                         :: "r"(base + SMEM_BAR_OFF + s * 16) : "memory");
            step_item(m, i, j);
        }
        return;
    }

    // ---------------- consumers ----------------
    const int m_base = (wid & 3) * 32;
    const int jslab  = wid >> 2;
    const uint32_t rB0 = (uint32_t)(jslab * 64 + (lane & 7) + ((lane >> 4) << 3));
    const uint32_t gB  = (uint32_t)((lane >> 3) & 1);

    uint32_t af[2][8][4];
    float s00 = 0.f, s01 = 0.f, s10 = 0.f, s11 = 0.f;
    int ati = -1, amat = 0;
    int m = mat, i = ti, j = tj;

    for (int k = 0; k < n_items; ++k) {
        const int s = k & 3, w = k >> 2;
        mbar_wait(base + SMEM_BAR_OFF + s * 16, (uint32_t)(w & 1));

        if (i != ati) {
            // flush accumulated row sums of the previous A-run
            if (ati >= 0) {
                float t0 = s00, t1 = s01, t2 = s10, t3 = s11;
#pragma unroll
                for (int o = 1; o <= 2; o <<= 1) {
                    t0 += __shfl_xor_sync(0xFFFFFFFFu, t0, o);
                    t1 += __shfl_xor_sync(0xFFFFFFFFu, t1, o);
                    t2 += __shfl_xor_sync(0xFFFFFFFFu, t2, o);
                    t3 += __shfl_xor_sync(0xFFFFFFFFu, t3, o);
                }
                if ((lane & 3) == 0) {
                    float* dst = &g_rowsum[amat][ati * 128 + m_base + (lane >> 2)];
                    atomicAdd(dst,      t0);
                    atomicAdd(dst + 8,  t1);
                    atomicAdd(dst + 16, t2);
                    atomicAdd(dst + 24, t3);
                }
                s00 = s01 = s10 = s11 = 0.f;
            }
            // load A fragments from global (documented mma fragment layout)
            const char* Ab = (const char*)(g_a + (size_t)i * 128 * NDIM);
            const uint32_t R = (uint32_t)(m_base + (lane >> 2));
            const uint32_t c0 = (uint32_t)((lane & 3) * 2);
#pragma unroll
            for (int mb = 0; mb < 2; ++mb)
#pragma unroll
                for (int kk = 0; kk < 8; ++kk) {
                    const char* p = Ab + (size_t)(R + mb * 16u) * 256 + kk * 32 + c0 * 2;
                    af[mb][kk][0] = *(const uint32_t*)p;
                    af[mb][kk][1] = *(const uint32_t*)(p + 8 * 256);
                    af[mb][kk][2] = *(const uint32_t*)(p + 16);
                    af[mb][kk][3] = *(const uint32_t*)(p + 8 * 256 + 16);
                }
            ati = i; amat = m;
        }

        const uint32_t bstage = base + (uint32_t)s * TILE_BYTES;
        float c[2][8][4];
#pragma unroll
        for (int mb = 0; mb < 2; ++mb)
#pragma unroll
            for (int n = 0; n < 8; ++n)
#pragma unroll
                for (int q = 0; q < 4; ++q) c[mb][n][q] = 0.f;

#pragma unroll
        for (int kk = 0; kk < 8; ++kk) {
            uint32_t bf[4][4];
#pragma unroll
            for (int nb = 0; nb < 4; ++nb) {
                uint32_t addr = tile_addr(bstage, rB0 + nb * 16u, 2u * kk + gB);
                ldsm_x4(bf[nb][0], bf[nb][1], bf[nb][2], bf[nb][3], addr);
            }
#pragma unroll
            for (int mb = 0; mb < 2; ++mb)
#pragma unroll
                for (int nb = 0; nb < 4; ++nb) {
                    mma_bf16(c[mb][nb * 2][0], c[mb][nb * 2][1],
                             c[mb][nb * 2][2], c[mb][nb * 2][3],
                             af[mb][kk][0], af[mb][kk][1], af[mb][kk][2], af[mb][kk][3],
                             bf[nb][0], bf[nb][1]);
                    mma_bf16(c[mb][nb * 2 + 1][0], c[mb][nb * 2 + 1][1],
                             c[mb][nb * 2 + 1][2], c[mb][nb * 2 + 1][3],
                             af[mb][kk][0], af[mb][kk][1], af[mb][kk][2], af[mb][kk][3],
                             bf[nb][2], bf[nb][3]);
                }
        }
        __syncwarp();
        if (lane == 0) mbar_arrive(base + SMEM_BAR_OFF + s * 16 + 8);

        // epilogue: exp + row sums (+ col credits for S11 off-diag)
        const bool do_col = (m == 1) && (i != j);
#pragma unroll
        for (int n = 0; n < 8; ++n) {
            float e00 = ex2f(c[0][n][0]), e01 = ex2f(c[0][n][1]);
            float e02 = ex2f(c[0][n][2]), e03 = ex2f(c[0][n][3]);
            float e10 = ex2f(c[1][n][0]), e11 = ex2f(c[1][n][1]);
            float e12 = ex2f(c[1][n][2]), e13 = ex2f(c[1][n][3]);
            s00 += e00 + e01; s01 += e02 + e03;
            s10 += e10 + e11; s11 += e12 + e13;
            if (do_col) {
                float col0 = e00 + e02 + e10 + e12;   // col n*8 + (lane&3)*2
                float col1 = e01 + e03 + e11 + e13;   // col n*8 + (lane&3)*2 + 1
#pragma unroll
                for (int o = 4; o <= 16; o <<= 1) {
                    col0 += __shfl_xor_sync(0xFFFFFFFFu, col0, o);
                    col1 += __shfl_xor_sync(0xFFFFFFFFu, col1, o);
                }
                if (lane < 4) {
                    float* dst = &g_rowsum[1][j * 128 + jslab * 64 + lane * 2 + n * 8];
                    atomicAdd(dst,     col0);
                    atomicAdd(dst + 1, col1);
                }
            }
        }
        step_item(m, i, j);
    }

    // final flush
    if (ati >= 0) {
#pragma unroll
        for (int o = 1; o <= 2; o <<= 1) {
            s00 += __shfl_xor_sync(0xFFFFFFFFu, s00, o);
            s01 += __shfl_xor_sync(0xFFFFFFFFu, s01, o);
            s10 += __shfl_xor_sync(0xFFFFFFFFu, s10, o);
            s11 += __shfl_xor_sync(0xFFFFFFFFu, s11, o);
        }
        if ((lane & 3) == 0) {
            float* dst = &g_rowsum[amat][ati * 128 + m_base + (lane >> 2)];
            atomicAdd(dst,      s00);
            atomicAdd(dst + 8,  s01);
            atomicAdd(dst + 16, s10);
            atomicAdd(dst + 24, s11);
        }
    }
}

// ---------------- kernel C: final reduction ----------------
__global__ void __launch_bounds__(256) finish_kernel(float* __restrict__ out) {
    __shared__ float sc[256], sa[256];
    int tid = threadIdx.x;
    float c = 0.f, a = 0.f;
    for (int r = tid; r < NROWS; r += 256) {
        float num  = ex2f(EXP_SCALE * g_d12[r]);
        float diag = ex2f(EXP_SCALE * g_d11[r]);
        float den  = g_rowsum[0][r] + g_rowsum[1][r] - diag;
        c -= logf(1e-12f + num / den);
        a += g_adv[r];
    }
    sc[tid] = c; sa[tid] = a;
    __syncthreads();
    for (int st = 128; st > 0; st >>= 1) {
        if (tid < st) { sc[tid] += sc[tid + st]; sa[tid] += sa[tid + st]; }
        __syncthreads();
    }
    if (tid == 0)
        out[0] = sc[0] / (8192.0f * 16383.0f) + sa[0];
}

extern "C" void kernel_launch(void* const* d_in, const int* in_sizes, int n_in,
                              void* d_out, int out_size) {
    const float* z1  = (const float*)d_in[0];
    const float* z2  = (const float*)d_in[1];
    const float* c   = (const float*)d_in[2];
    const float* lab = (const float*)d_in[3];
    cudaFuncSetAttribute(sim_rowsum_kernel,
                         cudaFuncAttributeMaxDynamicSharedMemorySize, SMEM_DYN);
    prep_kernel<<<NROWS / 8, 256>>>(z1, z2, c, lab);
    sim_rowsum_kernel<<<NCTA, 320, SMEM_DYN>>>();
    finish_kernel<<<1, 256>>>((float*)d_out);
}

// round 13
// speedup vs baseline: 1.2906x; 1.1150x over previous
#include <cuda_runtime.h>
#include <cuda_bf16.h>
#include <cstdint>

#define NROWS 8192
#define NDIM  128
#define NS    64

static constexpr float EXP_SCALE = 14.4269504088896340736f; // log2(e)/tau
static constexpr int TOTAL_ITEMS = 8192;   // 64 rows x 2 mats x 64 B-tiles
static constexpr int NCTA = 148;

// ---------------- device scratch (bf16 operands) ----------------
__device__ __align__(256) __nv_bfloat16 g_a [NROWS * NDIM];  // n1 * log2(e)/tau
__device__ __align__(256) __nv_bfloat16 g_b1[NROWS * NDIM];  // n1
__device__ __align__(256) __nv_bfloat16 g_b2[NROWS * NDIM];  // n2
__device__ float g_d12[NROWS];
__device__ float g_d11[NROWS];
__device__ float g_adv[NROWS];
__device__ float g_rowsum[2][NROWS];

// ---------------- helpers ----------------
__device__ __forceinline__ uint32_t smem_u32(const void* p) {
    uint32_t a;
    asm("{ .reg .u64 t; cvta.to.shared.u64 t, %1; cvt.u32.u64 %0, t; }" : "=r"(a) : "l"(p));
    return a;
}
__device__ __forceinline__ float warp_sum(float v) {
#pragma unroll
    for (int o = 16; o > 0; o >>= 1) v += __shfl_xor_sync(0xFFFFFFFFu, v, o);
    return v;
}
__device__ __forceinline__ float ex2f(float x) {
    float y; asm("ex2.approx.f32 %0, %1;" : "=f"(y) : "f"(x)); return y;
}
__device__ __forceinline__ void ldsm_x4(uint32_t& r0, uint32_t& r1, uint32_t& r2, uint32_t& r3,
                                        uint32_t addr) {
    asm volatile("ldmatrix.sync.aligned.m8n8.x4.shared.b16 {%0,%1,%2,%3}, [%4];"
                 : "=r"(r0), "=r"(r1), "=r"(r2), "=r"(r3) : "r"(addr));
}
__device__ __forceinline__ void mma_bf16(float& c0, float& c1, float& c2, float& c3,
                                         uint32_t a0, uint32_t a1, uint32_t a2, uint32_t a3,
                                         uint32_t b0, uint32_t b1) {
    asm volatile(
        "mma.sync.aligned.m16n8k16.row.col.f32.bf16.bf16.f32 "
        "{%0,%1,%2,%3},{%4,%5,%6,%7},{%8,%9},{%0,%1,%2,%3};"
        : "+f"(c0), "+f"(c1), "+f"(c2), "+f"(c3)
        : "r"(a0), "r"(a1), "r"(a2), "r"(a3), "r"(b0), "r"(b1));
}
__device__ __forceinline__ void mbar_init(uint32_t a, uint32_t c) {
    asm volatile("mbarrier.init.shared.b64 [%0], %1;" :: "r"(a), "r"(c) : "memory");
}
__device__ __forceinline__ void mbar_wait(uint32_t a, uint32_t par) {
    asm volatile(
        "{\n\t.reg .pred P1;\n\t"
        "W_%=:\n\t"
        "mbarrier.try_wait.parity.acquire.cta.shared::cta.b64 P1, [%0], %1, 0x989680;\n\t"
        "@P1 bra.uni D_%=;\n\t"
        "bra.uni W_%=;\n\t"
        "D_%=:\n\t}"
        :: "r"(a), "r"(par) : "memory");
}
__device__ __forceinline__ void mbar_arrive(uint32_t a) {
    asm volatile("mbarrier.arrive.shared.b64 _, [%0];" :: "r"(a) : "memory");
}

// bf16 tile: 128 rows x 256B, 16 chunks(16B)/row, chunk swizzle c ^= (row&7)
__device__ __forceinline__ uint32_t tile_addr(uint32_t base, uint32_t row, uint32_t chunk) {
    return base + row * 256u + ((chunk ^ (row & 7u)) << 4);
}

static constexpr int TILE_BYTES   = 32768;
static constexpr int SMEM_BAR_OFF = 4 * TILE_BYTES;   // 4 B stages
static constexpr int SMEM_DYN     = SMEM_BAR_OFF + 128;

// item idx in [0, 8192): r = idx>>7 (A row-tile), mat = (idx>>6)&1, tj = idx&63
// (both mats of a row share the same A tile -> at most 1 A reload per CTA range)

// ---------------- kernel A: normalize + diagonals + adversarial + zeroing ----
__global__ void __launch_bounds__(256) prep_kernel(const float* __restrict__ z1,
                                                   const float* __restrict__ z2,
                                                   const float* __restrict__ cpre,
                                                   const float* __restrict__ lab) {
    int gtid = blockIdx.x * 256 + threadIdx.x;
    if (gtid < 2 * NROWS) ((float*)g_rowsum)[gtid] = 0.f;

    int w = threadIdx.x >> 5, lane = threadIdx.x & 31;
    int row = blockIdx.x * 8 + w;
    float4 a = ((const float4*)(z1 + (size_t)row * NDIM))[lane];
    float4 b = ((const float4*)(z2 + (size_t)row * NDIM))[lane];
    float ss1 = warp_sum(a.x * a.x + a.y * a.y + a.z * a.z + a.w * a.w);
    float ss2 = warp_sum(b.x * b.x + b.y * b.y + b.z * b.z + b.w * b.w);
    float inv1 = 1.f / fmaxf(sqrtf(ss1), 1e-8f);
    float inv2 = 1.f / fmaxf(sqrtf(ss2), 1e-8f);
    float4 n1 = make_float4(a.x * inv1, a.y * inv1, a.z * inv1, a.w * inv1);
    float4 n2 = make_float4(b.x * inv2, b.y * inv2, b.z * inv2, b.w * inv2);
    float d12 = warp_sum(n1.x * n2.x + n1.y * n2.y + n1.z * n2.z + n1.w * n2.w);
    float d11 = warp_sum(n1.x * n1.x + n1.y * n1.y + n1.z * n1.z + n1.w * n1.w);

    __nv_bfloat162* pa = (__nv_bfloat162*)(g_a + (size_t)row * NDIM) + lane * 2;
    pa[0] = __floats2bfloat162_rn(n1.x * EXP_SCALE, n1.y * EXP_SCALE);
    pa[1] = __floats2bfloat162_rn(n1.z * EXP_SCALE, n1.w * EXP_SCALE);
    __nv_bfloat162* p1 = (__nv_bfloat162*)(g_b1 + (size_t)row * NDIM) + lane * 2;
    p1[0] = __floats2bfloat162_rn(n1.x, n1.y);
    p1[1] = __floats2bfloat162_rn(n1.z, n1.w);
    __nv_bfloat162* p2 = (__nv_bfloat162*)(g_b2 + (size_t)row * NDIM) + lane * 2;
    p2[0] = __floats2bfloat162_rn(n2.x, n2.y);
    p2[1] = __floats2bfloat162_rn(n2.z, n2.w);
    if (lane == 0) { g_d12[row] = d12; g_d11[row] = d11; }

    float2 cc = ((const float2*)(cpre + (size_t)row * NS))[lane];
    float2 ll = ((const float2*)(lab + (size_t)row * NS))[lane];
    float csum = warp_sum(cc.x * cc.x + cc.y * cc.y);
    float bv = ll.x; int bi = lane * 2; float bc = cc.x;
    if (ll.y > bv) { bv = ll.y; bi = lane * 2 + 1; bc = cc.y; }
#pragma unroll
    for (int o = 16; o > 0; o >>= 1) {
        float ov = __shfl_xor_sync(0xFFFFFFFFu, bv, o);
        int   oi = __shfl_xor_sync(0xFFFFFFFFu, bi, o);
        float oc = __shfl_xor_sync(0xFFFFFFFFu, bc, o);
        if (ov > bv || (ov == bv && oi < bi)) { bv = ov; bi = oi; bc = oc; }
    }
    if (lane == 0) {
        float picked = bc / fmaxf(sqrtf(csum), 1e-12f);
        g_adv[row] = -logf(1e-12f + 1.f - picked);
    }
}

// ---------------- kernel B: static-schedule warp-specialized sim + exp sums ----
// 148 CTAs x 320 threads (8 consumer warps + 2 producer warps), 4-stage ring,
// no block sync in the main loop. Warps 4-7 phase-staggered vs 0-3 so each
// SMSP overlaps one warp's MUFU epilogue under the other's HMMA phase.
__global__ void __launch_bounds__(320, 1) sim_rowsum_kernel() {
    extern __shared__ char smem_raw[];
    const uint32_t base = smem_u32(smem_raw);
    const int tid = threadIdx.x, wid = tid >> 5, lane = tid & 31;
    const int k0 = (int)(((long long)blockIdx.x * TOTAL_ITEMS) / NCTA);
    const int k1 = (int)(((long long)(blockIdx.x + 1) * TOTAL_ITEMS) / NCTA);
    const int n_items = k1 - k0;

    if (tid == 0) {
#pragma unroll
        for (int s = 0; s < 4; ++s) {
            mbar_init(base + SMEM_BAR_OFF + s * 16, 64);      // full: 64 producer threads
            mbar_init(base + SMEM_BAR_OFF + s * 16 + 8, 8);   // empty: 8 consumer warps
        }
    }
    __syncthreads();

    if (wid >= 8) {
        // ---------------- producers: stream B tiles ----------------
        const int pid = tid - 256;                 // 0..63
        for (int k = 0; k < n_items; ++k) {
            const int idx = k0 + k;
            const int mt = (idx >> 6) & 1, tj = idx & 63;
            const int s = k & 3, w = k >> 2;
            mbar_wait(base + SMEM_BAR_OFF + s * 16 + 8, 1u ^ (uint32_t)(w & 1));
            const char* src = (const char*)((mt ? g_b1 : g_b2) + (size_t)tj * 128 * NDIM);
            const uint32_t stg = base + (uint32_t)s * TILE_BYTES;
#pragma unroll
            for (int jj = 0; jj < 32; ++jj) {
                uint32_t q = (uint32_t)pid + 64u * jj;
                uint32_t r = q >> 4, c = q & 15u;
                uint32_t d = tile_addr(stg, r, c);
                asm volatile("cp.async.cg.shared.global [%0], [%1], 16;"
                             :: "r"(d), "l"(src + ((size_t)r << 8) + ((size_t)c << 4)) : "memory");
            }
            asm volatile("cp.async.mbarrier.arrive.noinc.shared::cta.b64 [%0];"
                         :: "r"(base + SMEM_BAR_OFF + s * 16) : "memory");
        }
        return;
    }

    // ---------------- consumers ----------------
    const int m_base = (wid & 3) * 32;
    const int jslab  = wid >> 2;
    const uint32_t rB0 = (uint32_t)(jslab * 64 + (lane & 7) + ((lane >> 4) << 3));
    const uint32_t gB  = (uint32_t)((lane >> 3) & 1);

    // phase stagger: one SMSP hosts warp w and w+4; delay the upper group once
    if (wid >= 4) __nanosleep(700);

    uint32_t af[2][8][4];
    float s00 = 0.f, s01 = 0.f, s10 = 0.f, s11 = 0.f;
    int akey = -1, ar = -1;

    for (int k = 0; k < n_items; ++k) {
        const int idx = k0 + k;
        const int r = idx >> 7, mt = (idx >> 6) & 1;
        const int s = k & 3, w = k >> 2;
        mbar_wait(base + SMEM_BAR_OFF + s * 16, (uint32_t)(w & 1));

        const int key = (r << 1) | mt;
        if (key != akey) {
            // flush accumulated row sums of the previous (row, mat) run
            if (akey >= 0) {
                float t0 = s00, t1 = s01, t2 = s10, t3 = s11;
#pragma unroll
                for (int o = 1; o <= 2; o <<= 1) {
                    t0 += __shfl_xor_sync(0xFFFFFFFFu, t0, o);
                    t1 += __shfl_xor_sync(0xFFFFFFFFu, t1, o);
                    t2 += __shfl_xor_sync(0xFFFFFFFFu, t2, o);
                    t3 += __shfl_xor_sync(0xFFFFFFFFu, t3, o);
                }
                if ((lane & 3) == 0) {
                    float* dst = &g_rowsum[akey & 1][(akey >> 1) * 128 + m_base + (lane >> 2)];
                    atomicAdd(dst,      t0);
                    atomicAdd(dst + 8,  t1);
                    atomicAdd(dst + 16, t2);
                    atomicAdd(dst + 24, t3);
                }
                s00 = s01 = s10 = s11 = 0.f;
            }
            if (r != ar) {
                // load A fragments from global (mma fragment layout, R12-validated)
                const char* Ab = (const char*)(g_a + (size_t)r * 128 * NDIM);
                const uint32_t R = (uint32_t)(m_base + (lane >> 2));
                const uint32_t c0 = (uint32_t)((lane & 3) * 2);
#pragma unroll
                for (int mb = 0; mb < 2; ++mb)
#pragma unroll
                    for (int kk = 0; kk < 8; ++kk) {
                        const char* p = Ab + (size_t)(R + mb * 16u) * 256 + kk * 32 + c0 * 2;
                        af[mb][kk][0] = *(const uint32_t*)p;
                        af[mb][kk][1] = *(const uint32_t*)(p + 8 * 256);
                        af[mb][kk][2] = *(const uint32_t*)(p + 16);
                        af[mb][kk][3] = *(const uint32_t*)(p + 8 * 256 + 16);
                    }
                ar = r;
            }
            akey = key;
        }

        const uint32_t bstage = base + (uint32_t)s * TILE_BYTES;
        float c[2][8][4];
#pragma unroll
        for (int mb = 0; mb < 2; ++mb)
#pragma unroll
            for (int n = 0; n < 8; ++n)
#pragma unroll
                for (int q = 0; q < 4; ++q) c[mb][n][q] = 0.f;

#pragma unroll
        for (int kk = 0; kk < 8; ++kk) {
            uint32_t bf[4][4];
#pragma unroll
            for (int nb = 0; nb < 4; ++nb) {
                uint32_t addr = tile_addr(bstage, rB0 + nb * 16u, 2u * kk + gB);
                ldsm_x4(bf[nb][0], bf[nb][1], bf[nb][2], bf[nb][3], addr);
            }
#pragma unroll
            for (int mb = 0; mb < 2; ++mb)
#pragma unroll
                for (int nb = 0; nb < 4; ++nb) {
                    mma_bf16(c[mb][nb * 2][0], c[mb][nb * 2][1],
                             c[mb][nb * 2][2], c[mb][nb * 2][3],
                             af[mb][kk][0], af[mb][kk][1], af[mb][kk][2], af[mb][kk][3],
                             bf[nb][0], bf[nb][1]);
                    mma_bf16(c[mb][nb * 2 + 1][0], c[mb][nb * 2 + 1][1],
                             c[mb][nb * 2 + 1][2], c[mb][nb * 2 + 1][3],
                             af[mb][kk][0], af[mb][kk][1], af[mb][kk][2], af[mb][kk][3],
                             bf[nb][2], bf[nb][3]);
                }
        }
        __syncwarp();
        if (lane == 0) mbar_arrive(base + SMEM_BAR_OFF + s * 16 + 8);

        // epilogue: fp32 exp2 + row accumulation
#pragma unroll
        for (int n = 0; n < 8; ++n) {
            s00 += ex2f(c[0][n][0]) + ex2f(c[0][n][1]);
            s01 += ex2f(c[0][n][2]) + ex2f(c[0][n][3]);
            s10 += ex2f(c[1][n][0]) + ex2f(c[1][n][1]);
            s11 += ex2f(c[1][n][2]) + ex2f(c[1][n][3]);
        }
    }

    // final flush
    if (akey >= 0) {
#pragma unroll
        for (int o = 1; o <= 2; o <<= 1) {
            s00 += __shfl_xor_sync(0xFFFFFFFFu, s00, o);
            s01 += __shfl_xor_sync(0xFFFFFFFFu, s01, o);
            s10 += __shfl_xor_sync(0xFFFFFFFFu, s10, o);
            s11 += __shfl_xor_sync(0xFFFFFFFFu, s11, o);
        }
        if ((lane & 3) == 0) {
            float* dst = &g_rowsum[akey & 1][(akey >> 1) * 128 + m_base + (lane >> 2)];
            atomicAdd(dst,      s00);
            atomicAdd(dst + 8,  s01);
            atomicAdd(dst + 16, s10);
            atomicAdd(dst + 24, s11);
        }
    }
}

// ---------------- kernel C: final reduction ----------------
__global__ void __launch_bounds__(256) finish_kernel(float* __restrict__ out) {
    __shared__ float sc[256], sa[256];
    int tid = threadIdx.x;
    float c = 0.f, a = 0.f;
    for (int r = tid; r < NROWS; r += 256) {
        float num  = ex2f(EXP_SCALE * g_d12[r]);
        float diag = ex2f(EXP_SCALE * g_d11[r]);
        float den  = g_rowsum[0][r] + g_rowsum[1][r] - diag;
        c -= logf(1e-12f + num / den);
        a += g_adv[r];
    }
    sc[tid] = c; sa[tid] = a;
    __syncthreads();
    for (int st = 128; st > 0; st >>= 1) {
        if (tid < st) { sc[tid] += sc[tid + st]; sa[tid] += sa[tid + st]; }
        __syncthreads();
    }
    if (tid == 0)
        out[0] = sc[0] / (8192.0f * 16383.0f) + sa[0];
}

extern "C" void kernel_launch(void* const* d_in, const int* in_sizes, int n_in,
                              void* d_out, int out_size) {
    const float* z1  = (const float*)d_in[0];
    const float* z2  = (const float*)d_in[1];
    const float* c   = (const float*)d_in[2];
    const float* lab = (const float*)d_in[3];
    cudaFuncSetAttribute(sim_rowsum_kernel,
                         cudaFuncAttributeMaxDynamicSharedMemorySize, SMEM_DYN);
    prep_kernel<<<NROWS / 8, 256>>>(z1, z2, c, lab);
    sim_rowsum_kernel<<<NCTA, 320, SMEM_DYN>>>();
    finish_kernel<<<1, 256>>>((float*)d_out);
}

// round 14
// speedup vs baseline: 1.3637x; 1.0566x over previous
#include <cuda_runtime.h>
#include <cuda_bf16.h>
#include <cstdint>

#define NROWS 8192
#define NDIM  128
#define NS    64

static constexpr float EXP_SCALE = 14.4269504088896340736f; // log2(e)/tau
static constexpr int TOTAL_ITEMS = 8192;   // 64 rows x 2 mats x 64 B-tiles
static constexpr int NCTA = 148;
static constexpr int NSTG = 6;

// ---------------- device scratch (bf16 operands) ----------------
__device__ __align__(256) __nv_bfloat16 g_a [NROWS * NDIM];  // n1 * log2(e)/tau
__device__ __align__(256) __nv_bfloat16 g_b1[NROWS * NDIM];  // n1
__device__ __align__(256) __nv_bfloat16 g_b2[NROWS * NDIM];  // n2
__device__ float g_d12[NROWS];
__device__ float g_d11[NROWS];
__device__ float g_adv[NROWS];
__device__ float g_rowsum[2][NROWS];

// ---------------- helpers ----------------
__device__ __forceinline__ uint32_t smem_u32(const void* p) {
    uint32_t a;
    asm("{ .reg .u64 t; cvta.to.shared.u64 t, %1; cvt.u32.u64 %0, t; }" : "=r"(a) : "l"(p));
    return a;
}
__device__ __forceinline__ float warp_sum(float v) {
#pragma unroll
    for (int o = 16; o > 0; o >>= 1) v += __shfl_xor_sync(0xFFFFFFFFu, v, o);
    return v;
}
__device__ __forceinline__ float ex2f(float x) {
    float y; asm("ex2.approx.f32 %0, %1;" : "=f"(y) : "f"(x)); return y;
}
// exp2(x), exp2(y) via one f16x2 MUFU op, accumulate both into s (fp32)
__device__ __forceinline__ void exp2_acc(float& s, float x, float y) {
    uint32_t h, e;
    asm("cvt.rn.f16x2.f32 %0, %1, %2;" : "=r"(h) : "f"(x), "f"(y));
    asm("ex2.approx.f16x2 %0, %1;" : "=r"(e) : "r"(h));
    float fx, fy;
    asm("{.reg .b16 l,u; mov.b32 {l,u}, %2; cvt.f32.f16 %0, l; cvt.f32.f16 %1, u;}"
        : "=f"(fx), "=f"(fy) : "r"(e));
    s += fx + fy;
}
__device__ __forceinline__ void ldsm_x4(uint32_t& r0, uint32_t& r1, uint32_t& r2, uint32_t& r3,
                                        uint32_t addr) {
    asm volatile("ldmatrix.sync.aligned.m8n8.x4.shared.b16 {%0,%1,%2,%3}, [%4];"
                 : "=r"(r0), "=r"(r1), "=r"(r2), "=r"(r3) : "r"(addr));
}
__device__ __forceinline__ void mma_bf16(float& c0, float& c1, float& c2, float& c3,
                                         uint32_t a0, uint32_t a1, uint32_t a2, uint32_t a3,
                                         uint32_t b0, uint32_t b1) {
    asm volatile(
        "mma.sync.aligned.m16n8k16.row.col.f32.bf16.bf16.f32 "
        "{%0,%1,%2,%3},{%4,%5,%6,%7},{%8,%9},{%0,%1,%2,%3};"
        : "+f"(c0), "+f"(c1), "+f"(c2), "+f"(c3)
        : "r"(a0), "r"(a1), "r"(a2), "r"(a3), "r"(b0), "r"(b1));
}
__device__ __forceinline__ void mbar_init(uint32_t a, uint32_t c) {
    asm volatile("mbarrier.init.shared.b64 [%0], %1;" :: "r"(a), "r"(c) : "memory");
}
__device__ __forceinline__ void mbar_wait(uint32_t a, uint32_t par) {
    asm volatile(
        "{\n\t.reg .pred P1;\n\t"
        "W_%=:\n\t"
        "mbarrier.try_wait.parity.acquire.cta.shared::cta.b64 P1, [%0], %1, 0x989680;\n\t"
        "@P1 bra.uni D_%=;\n\t"
        "bra.uni W_%=;\n\t"
        "D_%=:\n\t}"
        :: "r"(a), "r"(par) : "memory");
}
__device__ __forceinline__ void mbar_arrive(uint32_t a) {
    asm volatile("mbarrier.arrive.shared.b64 _, [%0];" :: "r"(a) : "memory");
}

// bf16 tile: 128 rows x 256B, 16 chunks(16B)/row, chunk swizzle c ^= (row&7)
__device__ __forceinline__ uint32_t tile_addr(uint32_t base, uint32_t row, uint32_t chunk) {
    return base + row * 256u + ((chunk ^ (row & 7u)) << 4);
}

static constexpr int TILE_BYTES   = 32768;
static constexpr int SMEM_BAR_OFF = NSTG * TILE_BYTES;   // 6 B stages = 192KB
static constexpr int SMEM_DYN     = SMEM_BAR_OFF + 128;

// item idx in [0, 8192): r = idx>>7 (A row-tile), mat = (idx>>6)&1, tj = idx&63

// ---------------- kernel A: normalize + diagonals + adversarial + zeroing ----
__global__ void __launch_bounds__(256) prep_kernel(const float* __restrict__ z1,
                                                   const float* __restrict__ z2,
                                                   const float* __restrict__ cpre,
                                                   const float* __restrict__ lab) {
    int gtid = blockIdx.x * 256 + threadIdx.x;
    if (gtid < 2 * NROWS) ((float*)g_rowsum)[gtid] = 0.f;

    int w = threadIdx.x >> 5, lane = threadIdx.x & 31;
    int row = blockIdx.x * 8 + w;
    float4 a = ((const float4*)(z1 + (size_t)row * NDIM))[lane];
    float4 b = ((const float4*)(z2 + (size_t)row * NDIM))[lane];
    float ss1 = warp_sum(a.x * a.x + a.y * a.y + a.z * a.z + a.w * a.w);
    float ss2 = warp_sum(b.x * b.x + b.y * b.y + b.z * b.z + b.w * b.w);
    float inv1 = 1.f / fmaxf(sqrtf(ss1), 1e-8f);
    float inv2 = 1.f / fmaxf(sqrtf(ss2), 1e-8f);
    float4 n1 = make_float4(a.x * inv1, a.y * inv1, a.z * inv1, a.w * inv1);
    float4 n2 = make_float4(b.x * inv2, b.y * inv2, b.z * inv2, b.w * inv2);
    float d12 = warp_sum(n1.x * n2.x + n1.y * n2.y + n1.z * n2.z + n1.w * n2.w);
    float d11 = warp_sum(n1.x * n1.x + n1.y * n1.y + n1.z * n1.z + n1.w * n1.w);

    __nv_bfloat162* pa = (__nv_bfloat162*)(g_a + (size_t)row * NDIM) + lane * 2;
    pa[0] = __floats2bfloat162_rn(n1.x * EXP_SCALE, n1.y * EXP_SCALE);
    pa[1] = __floats2bfloat162_rn(n1.z * EXP_SCALE, n1.w * EXP_SCALE);
    __nv_bfloat162* p1 = (__nv_bfloat162*)(g_b1 + (size_t)row * NDIM) + lane * 2;
    p1[0] = __floats2bfloat162_rn(n1.x, n1.y);
    p1[1] = __floats2bfloat162_rn(n1.z, n1.w);
    __nv_bfloat162* p2 = (__nv_bfloat162*)(g_b2 + (size_t)row * NDIM) + lane * 2;
    p2[0] = __floats2bfloat162_rn(n2.x, n2.y);
    p2[1] = __floats2bfloat162_rn(n2.z, n2.w);
    if (lane == 0) { g_d12[row] = d12; g_d11[row] = d11; }

    float2 cc = ((const float2*)(cpre + (size_t)row * NS))[lane];
    float2 ll = ((const float2*)(lab + (size_t)row * NS))[lane];
    float csum = warp_sum(cc.x * cc.x + cc.y * cc.y);
    float bv = ll.x; int bi = lane * 2; float bc = cc.x;
    if (ll.y > bv) { bv = ll.y; bi = lane * 2 + 1; bc = cc.y; }
#pragma unroll
    for (int o = 16; o > 0; o >>= 1) {
        float ov = __shfl_xor_sync(0xFFFFFFFFu, bv, o);
        int   oi = __shfl_xor_sync(0xFFFFFFFFu, bi, o);
        float oc = __shfl_xor_sync(0xFFFFFFFFu, bc, o);
        if (ov > bv || (ov == bv && oi < bi)) { bv = ov; bi = oi; bc = oc; }
    }
    if (lane == 0) {
        float picked = bc / fmaxf(sqrtf(csum), 1e-12f);
        g_adv[row] = -logf(1e-12f + 1.f - picked);
    }
}

// ---------------- kernel B: static-schedule warp-specialized sim + exp sums ----
// 148 CTAs x 320 threads (8 consumer warps + 2 producer warps), 6-stage ring,
// no block sync in the main loop. Warps 4-7 staggered ~half a tile so each
// SMSP overlaps one warp's MUFU epilogue under the other's HMMA phase.
__global__ void __launch_bounds__(320, 1) sim_rowsum_kernel() {
    extern __shared__ char smem_raw[];
    const uint32_t base = smem_u32(smem_raw);
    const int tid = threadIdx.x, wid = tid >> 5, lane = tid & 31;
    const int k0 = (int)(((long long)blockIdx.x * TOTAL_ITEMS) / NCTA);
    const int k1 = (int)(((long long)(blockIdx.x + 1) * TOTAL_ITEMS) / NCTA);
    const int n_items = k1 - k0;

    if (tid == 0) {
#pragma unroll
        for (int s = 0; s < NSTG; ++s) {
            mbar_init(base + SMEM_BAR_OFF + s * 16, 64);      // full: 64 producer threads
            mbar_init(base + SMEM_BAR_OFF + s * 16 + 8, 8);   // empty: 8 consumer warps
        }
    }
    __syncthreads();

    if (wid >= 8) {
        // ---------------- producers: stream B tiles ----------------
        const int pid = tid - 256;                 // 0..63
        int s = 0, w = 0;
        for (int k = 0; k < n_items; ++k) {
            const int idx = k0 + k;
            const int mt = (idx >> 6) & 1, tj = idx & 63;
            mbar_wait(base + SMEM_BAR_OFF + s * 16 + 8, 1u ^ (uint32_t)(w & 1));
            const char* src = (const char*)((mt ? g_b1 : g_b2) + (size_t)tj * 128 * NDIM);
            const uint32_t stg = base + (uint32_t)s * TILE_BYTES;
#pragma unroll
            for (int jj = 0; jj < 32; ++jj) {
                uint32_t q = (uint32_t)pid + 64u * jj;
                uint32_t r = q >> 4, c = q & 15u;
                uint32_t d = tile_addr(stg, r, c);
                asm volatile("cp.async.cg.shared.global [%0], [%1], 16;"
                             :: "r"(d), "l"(src + ((size_t)r << 8) + ((size_t)c << 4)) : "memory");
            }
            asm volatile("cp.async.mbarrier.arrive.noinc.shared::cta.b64 [%0];"
                         :: "r"(base + SMEM_BAR_OFF + s * 16) : "memory");
            if (++s == NSTG) { s = 0; w ^= 1; }
        }
        return;
    }

    // ---------------- consumers ----------------
    const int m_base = (wid & 3) * 32;
    const int jslab  = wid >> 2;
    const uint32_t rB0 = (uint32_t)(jslab * 64 + (lane & 7) + ((lane >> 4) << 3));
    const uint32_t gB  = (uint32_t)((lane >> 3) & 1);

    // phase stagger: one SMSP hosts warp w and w+4; delay the upper group
    // by ~half a tile so MUFU epilogues interleave with HMMA phases.
    if (wid >= 4) __nanosleep(900);

    uint32_t af[2][8][4];
    float s00 = 0.f, s01 = 0.f, s10 = 0.f, s11 = 0.f;
    int akey = -1, ar = -1;
    int s = 0, w = 0;

    for (int k = 0; k < n_items; ++k) {
        const int idx = k0 + k;
        const int r = idx >> 7, mt = (idx >> 6) & 1;
        mbar_wait(base + SMEM_BAR_OFF + s * 16, (uint32_t)(w & 1));

        const int key = (r << 1) | mt;
        if (key != akey) {
            // flush accumulated row sums of the previous (row, mat) run
            if (akey >= 0) {
                float t0 = s00, t1 = s01, t2 = s10, t3 = s11;
#pragma unroll
                for (int o = 1; o <= 2; o <<= 1) {
                    t0 += __shfl_xor_sync(0xFFFFFFFFu, t0, o);
                    t1 += __shfl_xor_sync(0xFFFFFFFFu, t1, o);
                    t2 += __shfl_xor_sync(0xFFFFFFFFu, t2, o);
                    t3 += __shfl_xor_sync(0xFFFFFFFFu, t3, o);
                }
                if ((lane & 3) == 0) {
                    float* dst = &g_rowsum[akey & 1][(akey >> 1) * 128 + m_base + (lane >> 2)];
                    atomicAdd(dst,      t0);
                    atomicAdd(dst + 8,  t1);
                    atomicAdd(dst + 16, t2);
                    atomicAdd(dst + 24, t3);
                }
                s00 = s01 = s10 = s11 = 0.f;
            }
            if (r != ar) {
                // load A fragments from global (mma fragment layout, R12-validated)
                const char* Ab = (const char*)(g_a + (size_t)r * 128 * NDIM);
                const uint32_t R = (uint32_t)(m_base + (lane >> 2));
                const uint32_t c0 = (uint32_t)((lane & 3) * 2);
#pragma unroll
                for (int mb = 0; mb < 2; ++mb)
#pragma unroll
                    for (int kk = 0; kk < 8; ++kk) {
                        const char* p = Ab + (size_t)(R + mb * 16u) * 256 + kk * 32 + c0 * 2;
                        af[mb][kk][0] = *(const uint32_t*)p;
                        af[mb][kk][1] = *(const uint32_t*)(p + 8 * 256);
                        af[mb][kk][2] = *(const uint32_t*)(p + 16);
                        af[mb][kk][3] = *(const uint32_t*)(p + 8 * 256 + 16);
                    }
                ar = r;
            }
            akey = key;
        }

        const uint32_t bstage = base + (uint32_t)s * TILE_BYTES;
        float c[2][8][4];
#pragma unroll
        for (int mb = 0; mb < 2; ++mb)
#pragma unroll
            for (int n = 0; n < 8; ++n)
#pragma unroll
                for (int q = 0; q < 4; ++q) c[mb][n][q] = 0.f;

#pragma unroll
        for (int kk = 0; kk < 8; ++kk) {
            uint32_t bf[4][4];
#pragma unroll
            for (int nb = 0; nb < 4; ++nb) {
                uint32_t addr = tile_addr(bstage, rB0 + nb * 16u, 2u * kk + gB);
                ldsm_x4(bf[nb][0], bf[nb][1], bf[nb][2], bf[nb][3], addr);
            }
#pragma unroll
            for (int mb = 0; mb < 2; ++mb)
#pragma unroll
                for (int nb = 0; nb < 4; ++nb) {
                    mma_bf16(c[mb][nb * 2][0], c[mb][nb * 2][1],
                             c[mb][nb * 2][2], c[mb][nb * 2][3],
                             af[mb][kk][0], af[mb][kk][1], af[mb][kk][2], af[mb][kk][3],
                             bf[nb][0], bf[nb][1]);
                    mma_bf16(c[mb][nb * 2 + 1][0], c[mb][nb * 2 + 1][1],
                             c[mb][nb * 2 + 1][2], c[mb][nb * 2 + 1][3],
                             af[mb][kk][0], af[mb][kk][1], af[mb][kk][2], af[mb][kk][3],
                             bf[nb][2], bf[nb][3]);
                }
        }
        __syncwarp();
        if (lane == 0) mbar_arrive(base + SMEM_BAR_OFF + s * 16 + 8);

        // epilogue: f16x2 exp2 + fp32 row accumulation (MUFU ops halved)
#pragma unroll
        for (int n = 0; n < 8; ++n) {
            exp2_acc(s00, c[0][n][0], c[0][n][1]);
            exp2_acc(s01, c[0][n][2], c[0][n][3]);
            exp2_acc(s10, c[1][n][0], c[1][n][1]);
            exp2_acc(s11, c[1][n][2], c[1][n][3]);
        }
        if (++s == NSTG) { s = 0; w ^= 1; }
    }

    // final flush
    if (akey >= 0) {
#pragma unroll
        for (int o = 1; o <= 2; o <<= 1) {
            s00 += __shfl_xor_sync(0xFFFFFFFFu, s00, o);
            s01 += __shfl_xor_sync(0xFFFFFFFFu, s01, o);
            s10 += __shfl_xor_sync(0xFFFFFFFFu, s10, o);
            s11 += __shfl_xor_sync(0xFFFFFFFFu, s11, o);
        }
        if ((lane & 3) == 0) {
            float* dst = &g_rowsum[akey & 1][(akey >> 1) * 128 + m_base + (lane >> 2)];
            atomicAdd(dst,      s00);
            atomicAdd(dst + 8,  s01);
            atomicAdd(dst + 16, s10);
            atomicAdd(dst + 24, s11);
        }
    }
}

// ---------------- kernel C: final reduction ----------------
__global__ void __launch_bounds__(256) finish_kernel(float* __restrict__ out) {
    __shared__ float sc[256], sa[256];
    int tid = threadIdx.x;
    float c = 0.f, a = 0.f;
    for (int r = tid; r < NROWS; r += 256) {
        float num  = ex2f(EXP_SCALE * g_d12[r]);
        float diag = ex2f(EXP_SCALE * g_d11[r]);
        float den  = g_rowsum[0][r] + g_rowsum[1][r] - diag;
        c -= logf(1e-12f + num / den);
        a += g_adv[r];
    }
    sc[tid] = c; sa[tid] = a;
    __syncthreads();
    for (int st = 128; st > 0; st >>= 1) {
        if (tid < st) { sc[tid] += sc[tid + st]; sa[tid] += sa[tid + st]; }
        __syncthreads();
    }
    if (tid == 0)
        out[0] = sc[0] / (8192.0f * 16383.0f) + sa[0];
}

extern "C" void kernel_launch(void* const* d_in, const int* in_sizes, int n_in,
                              void* d_out, int out_size) {
    const float* z1  = (const float*)d_in[0];
    const float* z2  = (const float*)d_in[1];
    const float* c   = (const float*)d_in[2];
    const float* lab = (const float*)d_in[3];
    cudaFuncSetAttribute(sim_rowsum_kernel,
                         cudaFuncAttributeMaxDynamicSharedMemorySize, SMEM_DYN);
    prep_kernel<<<NROWS / 8, 256>>>(z1, z2, c, lab);
    sim_rowsum_kernel<<<NCTA, 320, SMEM_DYN>>>();
    finish_kernel<<<1, 256>>>((float*)d_out);
}

// round 15
// speedup vs baseline: 1.4079x; 1.0324x over previous
#include <cuda_runtime.h>
#include <cuda_bf16.h>
#include <cstdint>

#define NROWS 8192
#define NDIM  128
#define NS    64

static constexpr float EXP_SCALE = 14.4269504088896340736f; // log2(e)/tau
static constexpr int TOTAL_ITEMS = 16384;  // 64 rows x 2 mats x 128 col-tiles(64)
static constexpr int NCTA = 296;           // 2 CTAs per SM
static constexpr int NSTG = 4;

// ---------------- device scratch (bf16 operands) ----------------
__device__ __align__(256) __nv_bfloat16 g_a [NROWS * NDIM];  // n1 * log2(e)/tau
__device__ __align__(256) __nv_bfloat16 g_b1[NROWS * NDIM];  // n1
__device__ __align__(256) __nv_bfloat16 g_b2[NROWS * NDIM];  // n2
__device__ float g_d12[NROWS];
__device__ float g_d11[NROWS];
__device__ float g_adv[NROWS];
__device__ float g_rowsum[2][NROWS];

// ---------------- helpers ----------------
__device__ __forceinline__ uint32_t smem_u32(const void* p) {
    uint32_t a;
    asm("{ .reg .u64 t; cvta.to.shared.u64 t, %1; cvt.u32.u64 %0, t; }" : "=r"(a) : "l"(p));
    return a;
}
__device__ __forceinline__ float warp_sum(float v) {
#pragma unroll
    for (int o = 16; o > 0; o >>= 1) v += __shfl_xor_sync(0xFFFFFFFFu, v, o);
    return v;
}
__device__ __forceinline__ float ex2f(float x) {
    float y; asm("ex2.approx.f32 %0, %1;" : "=f"(y) : "f"(x)); return y;
}
// exp2(x), exp2(y) via one f16x2 MUFU op, accumulate both into s (fp32)
__device__ __forceinline__ void exp2_acc(float& s, float x, float y) {
    uint32_t h, e;
    asm("cvt.rn.f16x2.f32 %0, %1, %2;" : "=r"(h) : "f"(x), "f"(y));
    asm("ex2.approx.f16x2 %0, %1;" : "=r"(e) : "r"(h));
    float fx, fy;
    asm("{.reg .b16 l,u; mov.b32 {l,u}, %2; cvt.f32.f16 %0, l; cvt.f32.f16 %1, u;}"
        : "=f"(fx), "=f"(fy) : "r"(e));
    s += fx + fy;
}
__device__ __forceinline__ void ldsm_x4(uint32_t& r0, uint32_t& r1, uint32_t& r2, uint32_t& r3,
                                        uint32_t addr) {
    asm volatile("ldmatrix.sync.aligned.m8n8.x4.shared.b16 {%0,%1,%2,%3}, [%4];"
                 : "=r"(r0), "=r"(r1), "=r"(r2), "=r"(r3) : "r"(addr));
}
__device__ __forceinline__ void mma_bf16(float& c0, float& c1, float& c2, float& c3,
                                         uint32_t a0, uint32_t a1, uint32_t a2, uint32_t a3,
                                         uint32_t b0, uint32_t b1) {
    asm volatile(
        "mma.sync.aligned.m16n8k16.row.col.f32.bf16.bf16.f32 "
        "{%0,%1,%2,%3},{%4,%5,%6,%7},{%8,%9},{%0,%1,%2,%3};"
        : "+f"(c0), "+f"(c1), "+f"(c2), "+f"(c3)
        : "r"(a0), "r"(a1), "r"(a2), "r"(a3), "r"(b0), "r"(b1));
}
__device__ __forceinline__ void mbar_init(uint32_t a, uint32_t c) {
    asm volatile("mbarrier.init.shared.b64 [%0], %1;" :: "r"(a), "r"(c) : "memory");
}
__device__ __forceinline__ void mbar_wait(uint32_t a, uint32_t par) {
    asm volatile(
        "{\n\t.reg .pred P1;\n\t"
        "W_%=:\n\t"
        "mbarrier.try_wait.parity.acquire.cta.shared::cta.b64 P1, [%0], %1, 0x989680;\n\t"
        "@P1 bra.uni D_%=;\n\t"
        "bra.uni W_%=;\n\t"
        "D_%=:\n\t}"
        :: "r"(a), "r"(par) : "memory");
}
__device__ __forceinline__ void mbar_arrive(uint32_t a) {
    asm volatile("mbarrier.arrive.shared.b64 _, [%0];" :: "r"(a) : "memory");
}

// bf16 tile: 64 rows x 256B, 16 chunks(16B)/row, chunk swizzle c ^= (row&7)
__device__ __forceinline__ uint32_t tile_addr(uint32_t base, uint32_t row, uint32_t chunk) {
    return base + row * 256u + ((chunk ^ (row & 7u)) << 4);
}

static constexpr int TILE_BYTES   = 16384;               // 64 B-rows x 256B
static constexpr int SMEM_BAR_OFF = NSTG * TILE_BYTES;   // 4 stages = 64KB
static constexpr int SMEM_DYN     = SMEM_BAR_OFF + 128;

// item idx in [0,16384): r = idx>>8 (A row-tile), mat = (idx>>7)&1, tj = idx&127

// ---------------- kernel A: normalize + diagonals + adversarial + zeroing ----
__global__ void __launch_bounds__(256) prep_kernel(const float* __restrict__ z1,
                                                   const float* __restrict__ z2,
                                                   const float* __restrict__ cpre,
                                                   const float* __restrict__ lab) {
    int gtid = blockIdx.x * 256 + threadIdx.x;
    if (gtid < 2 * NROWS) ((float*)g_rowsum)[gtid] = 0.f;

    int w = threadIdx.x >> 5, lane = threadIdx.x & 31;
    int row = blockIdx.x * 8 + w;
    float4 a = ((const float4*)(z1 + (size_t)row * NDIM))[lane];
    float4 b = ((const float4*)(z2 + (size_t)row * NDIM))[lane];
    float ss1 = warp_sum(a.x * a.x + a.y * a.y + a.z * a.z + a.w * a.w);
    float ss2 = warp_sum(b.x * b.x + b.y * b.y + b.z * b.z + b.w * b.w);
    float inv1 = 1.f / fmaxf(sqrtf(ss1), 1e-8f);
    float inv2 = 1.f / fmaxf(sqrtf(ss2), 1e-8f);
    float4 n1 = make_float4(a.x * inv1, a.y * inv1, a.z * inv1, a.w * inv1);
    float4 n2 = make_float4(b.x * inv2, b.y * inv2, b.z * inv2, b.w * inv2);
    float d12 = warp_sum(n1.x * n2.x + n1.y * n2.y + n1.z * n2.z + n1.w * n2.w);
    float d11 = warp_sum(n1.x * n1.x + n1.y * n1.y + n1.z * n1.z + n1.w * n1.w);

    __nv_bfloat162* pa = (__nv_bfloat162*)(g_a + (size_t)row * NDIM) + lane * 2;
    pa[0] = __floats2bfloat162_rn(n1.x * EXP_SCALE, n1.y * EXP_SCALE);
    pa[1] = __floats2bfloat162_rn(n1.z * EXP_SCALE, n1.w * EXP_SCALE);
    __nv_bfloat162* p1 = (__nv_bfloat162*)(g_b1 + (size_t)row * NDIM) + lane * 2;
    p1[0] = __floats2bfloat162_rn(n1.x, n1.y);
    p1[1] = __floats2bfloat162_rn(n1.z, n1.w);
    __nv_bfloat162* p2 = (__nv_bfloat162*)(g_b2 + (size_t)row * NDIM) + lane * 2;
    p2[0] = __floats2bfloat162_rn(n2.x, n2.y);
    p2[1] = __floats2bfloat162_rn(n2.z, n2.w);
    if (lane == 0) { g_d12[row] = d12; g_d11[row] = d11; }

    float2 cc = ((const float2*)(cpre + (size_t)row * NS))[lane];
    float2 ll = ((const float2*)(lab + (size_t)row * NS))[lane];
    float csum = warp_sum(cc.x * cc.x + cc.y * cc.y);
    float bv = ll.x; int bi = lane * 2; float bc = cc.x;
    if (ll.y > bv) { bv = ll.y; bi = lane * 2 + 1; bc = cc.y; }
#pragma unroll
    for (int o = 16; o > 0; o >>= 1) {
        float ov = __shfl_xor_sync(0xFFFFFFFFu, bv, o);
        int   oi = __shfl_xor_sync(0xFFFFFFFFu, bi, o);
        float oc = __shfl_xor_sync(0xFFFFFFFFu, bc, o);
        if (ov > bv || (ov == bv && oi < bi)) { bv = ov; bi = oi; bc = oc; }
    }
    if (lane == 0) {
        float picked = bc / fmaxf(sqrtf(csum), 1e-12f);
        g_adv[row] = -logf(1e-12f + 1.f - picked);
    }
}

// ---------------- kernel B: 2-CTA/SM warp-specialized sim + exp sums ----------
// 296 CTAs x 160 threads (4 consumer warps m32xn64 + 1 producer warp).
// Item = one 128x64 output tile. The two CTAs co-resident on an SM have
// independent rings/barriers -> their HMMA and MUFU phases interleave freely.
__global__ void __launch_bounds__(160, 2) sim_rowsum_kernel() {
    extern __shared__ char smem_raw[];
    const uint32_t base = smem_u32(smem_raw);
    const int tid = threadIdx.x, wid = tid >> 5, lane = tid & 31;
    const int k0 = (int)(((long long)blockIdx.x * TOTAL_ITEMS) / NCTA);
    const int k1 = (int)(((long long)(blockIdx.x + 1) * TOTAL_ITEMS) / NCTA);
    const int n_items = k1 - k0;

    if (tid == 0) {
#pragma unroll
        for (int s = 0; s < NSTG; ++s) {
            mbar_init(base + SMEM_BAR_OFF + s * 16, 32);      // full: 32 producer threads
            mbar_init(base + SMEM_BAR_OFF + s * 16 + 8, 4);   // empty: 4 consumer warps
        }
    }
    __syncthreads();

    if (wid == 4) {
        // ---------------- producer: stream 128x64 B tiles ----------------
        int s = 0, w = 0;
        for (int k = 0; k < n_items; ++k) {
            const int idx = k0 + k;
            const int mt = (idx >> 7) & 1, tj = idx & 127;
            mbar_wait(base + SMEM_BAR_OFF + s * 16 + 8, 1u ^ (uint32_t)(w & 1));
            const char* src = (const char*)((mt ? g_b1 : g_b2) + (size_t)tj * 64 * NDIM);
            const uint32_t stg = base + (uint32_t)s * TILE_BYTES;
#pragma unroll
            for (int jj = 0; jj < 32; ++jj) {
                uint32_t q = (uint32_t)lane + 32u * jj;   // 1024 16B chunks
                uint32_t r = q >> 4, c = q & 15u;
                uint32_t d = tile_addr(stg, r, c);
                asm volatile("cp.async.cg.shared.global [%0], [%1], 16;"
                             :: "r"(d), "l"(src + ((size_t)r << 8) + ((size_t)c << 4)) : "memory");
            }
            asm volatile("cp.async.mbarrier.arrive.noinc.shared::cta.b64 [%0];"
                         :: "r"(base + SMEM_BAR_OFF + s * 16) : "memory");
            if (++s == NSTG) { s = 0; w ^= 1; }
        }
        return;
    }

    // ---------------- consumers: 4 warps, m-slab 32 x n 64 each ----------------
    const int m_base = wid * 32;
    const uint32_t rB0 = (uint32_t)((lane & 7) + ((lane >> 4) << 3));
    const uint32_t gB  = (uint32_t)((lane >> 3) & 1);

    uint32_t af[2][8][4];
    float s00 = 0.f, s01 = 0.f, s10 = 0.f, s11 = 0.f;
    int akey = -1, ar = -1;
    int s = 0, w = 0;

    for (int k = 0; k < n_items; ++k) {
        const int idx = k0 + k;
        const int r = idx >> 8, mt = (idx >> 7) & 1;
        mbar_wait(base + SMEM_BAR_OFF + s * 16, (uint32_t)(w & 1));

        const int key = (r << 1) | mt;
        if (key != akey) {
            // flush accumulated row sums of the previous (row, mat) run
            if (akey >= 0) {
                float t0 = s00, t1 = s01, t2 = s10, t3 = s11;
#pragma unroll
                for (int o = 1; o <= 2; o <<= 1) {
                    t0 += __shfl_xor_sync(0xFFFFFFFFu, t0, o);
                    t1 += __shfl_xor_sync(0xFFFFFFFFu, t1, o);
                    t2 += __shfl_xor_sync(0xFFFFFFFFu, t2, o);
                    t3 += __shfl_xor_sync(0xFFFFFFFFu, t3, o);
                }
                if ((lane & 3) == 0) {
                    float* dst = &g_rowsum[akey & 1][(akey >> 1) * 128 + m_base + (lane >> 2)];
                    atomicAdd(dst,      t0);
                    atomicAdd(dst + 8,  t1);
                    atomicAdd(dst + 16, t2);
                    atomicAdd(dst + 24, t3);
                }
                s00 = s01 = s10 = s11 = 0.f;
            }
            if (r != ar) {
                // load A fragments from global (mma fragment layout, R12-validated)
                const char* Ab = (const char*)(g_a + (size_t)r * 128 * NDIM);
                const uint32_t R = (uint32_t)(m_base + (lane >> 2));
                const uint32_t c0 = (uint32_t)((lane & 3) * 2);
#pragma unroll
                for (int mb = 0; mb < 2; ++mb)
#pragma unroll
                    for (int kk = 0; kk < 8; ++kk) {
                        const char* p = Ab + (size_t)(R + mb * 16u) * 256 + kk * 32 + c0 * 2;
                        af[mb][kk][0] = *(const uint32_t*)p;
                        af[mb][kk][1] = *(const uint32_t*)(p + 8 * 256);
                        af[mb][kk][2] = *(const uint32_t*)(p + 16);
                        af[mb][kk][3] = *(const uint32_t*)(p + 8 * 256 + 16);
                    }
                ar = r;
            }
            akey = key;
        }

        const uint32_t bstage = base + (uint32_t)s * TILE_BYTES;
        float c[2][8][4];
#pragma unroll
        for (int mb = 0; mb < 2; ++mb)
#pragma unroll
            for (int n = 0; n < 8; ++n)
#pragma unroll
                for (int q = 0; q < 4; ++q) c[mb][n][q] = 0.f;

#pragma unroll
        for (int kk = 0; kk < 8; ++kk) {
            uint32_t bf[4][4];
#pragma unroll
            for (int nb = 0; nb < 4; ++nb) {
                uint32_t addr = tile_addr(bstage, rB0 + nb * 16u, 2u * kk + gB);
                ldsm_x4(bf[nb][0], bf[nb][1], bf[nb][2], bf[nb][3], addr);
            }
#pragma unroll
            for (int mb = 0; mb < 2; ++mb)
#pragma unroll
                for (int nb = 0; nb < 4; ++nb) {
                    mma_bf16(c[mb][nb * 2][0], c[mb][nb * 2][1],
                             c[mb][nb * 2][2], c[mb][nb * 2][3],
                             af[mb][kk][0], af[mb][kk][1], af[mb][kk][2], af[mb][kk][3],
                             bf[nb][0], bf[nb][1]);
                    mma_bf16(c[mb][nb * 2 + 1][0], c[mb][nb * 2 + 1][1],
                             c[mb][nb * 2 + 1][2], c[mb][nb * 2 + 1][3],
                             af[mb][kk][0], af[mb][kk][1], af[mb][kk][2], af[mb][kk][3],
                             bf[nb][2], bf[nb][3]);
                }
        }
        __syncwarp();
        if (lane == 0) mbar_arrive(base + SMEM_BAR_OFF + s * 16 + 8);

        // epilogue: f16x2 exp2 + fp32 row accumulation
#pragma unroll
        for (int n = 0; n < 8; ++n) {
            exp2_acc(s00, c[0][n][0], c[0][n][1]);
            exp2_acc(s01, c[0][n][2], c[0][n][3]);
            exp2_acc(s10, c[1][n][0], c[1][n][1]);
            exp2_acc(s11, c[1][n][2], c[1][n][3]);
        }
        if (++s == NSTG) { s = 0; w ^= 1; }
    }

    // final flush
    if (akey >= 0) {
#pragma unroll
        for (int o = 1; o <= 2; o <<= 1) {
            s00 += __shfl_xor_sync(0xFFFFFFFFu, s00, o);
            s01 += __shfl_xor_sync(0xFFFFFFFFu, s01, o);
            s10 += __shfl_xor_sync(0xFFFFFFFFu, s10, o);
            s11 += __shfl_xor_sync(0xFFFFFFFFu, s11, o);
        }
        if ((lane & 3) == 0) {
            float* dst = &g_rowsum[akey & 1][(akey >> 1) * 128 + m_base + (lane >> 2)];
            atomicAdd(dst,      s00);
            atomicAdd(dst + 8,  s01);
            atomicAdd(dst + 16, s10);
            atomicAdd(dst + 24, s11);
        }
    }
}

// ---------------- kernel C: final reduction ----------------
__global__ void __launch_bounds__(256) finish_kernel(float* __restrict__ out) {
    __shared__ float sc[256], sa[256];
    int tid = threadIdx.x;
    float c = 0.f, a = 0.f;
    for (int r = tid; r < NROWS; r += 256) {
        float num  = ex2f(EXP_SCALE * g_d12[r]);
        float diag = ex2f(EXP_SCALE * g_d11[r]);
        float den  = g_rowsum[0][r] + g_rowsum[1][r] - diag;
        c -= logf(1e-12f + num / den);
        a += g_adv[r];
    }
    sc[tid] = c; sa[tid] = a;
    __syncthreads();
    for (int st = 128; st > 0; st >>= 1) {
        if (tid < st) { sc[tid] += sc[tid + st]; sa[tid] += sa[tid + st]; }
        __syncthreads();
    }
    if (tid == 0)
        out[0] = sc[0] / (8192.0f * 16383.0f) + sa[0];
}

extern "C" void kernel_launch(void* const* d_in, const int* in_sizes, int n_in,
                              void* d_out, int out_size) {
    const float* z1  = (const float*)d_in[0];
    const float* z2  = (const float*)d_in[1];
    const float* c   = (const float*)d_in[2];
    const float* lab = (const float*)d_in[3];
    cudaFuncSetAttribute(sim_rowsum_kernel,
                         cudaFuncAttributeMaxDynamicSharedMemorySize, SMEM_DYN);
    prep_kernel<<<NROWS / 8, 256>>>(z1, z2, c, lab);
    sim_rowsum_kernel<<<NCTA, 160, SMEM_DYN>>>();
    finish_kernel<<<1, 256>>>((float*)d_out);
}

// round 16
// speedup vs baseline: 1.4230x; 1.0107x over previous
#include <cuda_runtime.h>
#include <cuda_fp16.h>
#include <cstdint>

#define NROWS 8192
#define NDIM  128
#define NS    64

static constexpr float EXP_SCALE = 14.4269504088896340736f; // log2(e)/tau
static constexpr int TOTAL_ITEMS = 16384;  // 64 rows x 2 mats x 128 col-tiles(64)
static constexpr int NCTA = 296;           // 2 CTAs per SM
static constexpr int NSTG = 4;

// ---------------- device scratch (fp16 operands) ----------------
__device__ __align__(256) __half g_a [NROWS * NDIM];  // n1 * log2(e)/tau
__device__ __align__(256) __half g_b1[NROWS * NDIM];  // n1
__device__ __align__(256) __half g_b2[NROWS * NDIM];  // n2
__device__ float g_d12[NROWS];
__device__ float g_d11[NROWS];
__device__ float g_adv[NROWS];
__device__ float g_rowsum[2][NROWS];

// ---------------- helpers ----------------
__device__ __forceinline__ uint32_t smem_u32(const void* p) {
    uint32_t a;
    asm("{ .reg .u64 t; cvta.to.shared.u64 t, %1; cvt.u32.u64 %0, t; }" : "=r"(a) : "l"(p));
    return a;
}
__device__ __forceinline__ float warp_sum(float v) {
#pragma unroll
    for (int o = 16; o > 0; o >>= 1) v += __shfl_xor_sync(0xFFFFFFFFu, v, o);
    return v;
}
__device__ __forceinline__ float ex2f(float x) {
    float y; asm("ex2.approx.f32 %0, %1;" : "=f"(y) : "f"(x)); return y;
}
// exp2 of both halves of a packed f16x2, accumulate into fp32 s
__device__ __forceinline__ void exp2h_acc(float& s, uint32_t h) {
    uint32_t e;
    asm("ex2.approx.f16x2 %0, %1;" : "=r"(e) : "r"(h));
    float fx, fy;
    asm("{.reg .b16 l,u; mov.b32 {l,u}, %2; cvt.f32.f16 %0, l; cvt.f32.f16 %1, u;}"
        : "=f"(fx), "=f"(fy) : "r"(e));
    s += fx + fy;
}
__device__ __forceinline__ void ldsm_x4(uint32_t& r0, uint32_t& r1, uint32_t& r2, uint32_t& r3,
                                        uint32_t addr) {
    asm volatile("ldmatrix.sync.aligned.m8n8.x4.shared.b16 {%0,%1,%2,%3}, [%4];"
                 : "=r"(r0), "=r"(r1), "=r"(r2), "=r"(r3) : "r"(addr));
}
// fp16-accumulator mma: D(f16x2 x2) = A(f16) * B(f16) + D
__device__ __forceinline__ void mma_f16(uint32_t& c0, uint32_t& c1,
                                        uint32_t a0, uint32_t a1, uint32_t a2, uint32_t a3,
                                        uint32_t b0, uint32_t b1) {
    asm volatile(
        "mma.sync.aligned.m16n8k16.row.col.f16.f16.f16.f16 "
        "{%0,%1},{%2,%3,%4,%5},{%6,%7},{%0,%1};"
        : "+r"(c0), "+r"(c1)
        : "r"(a0), "r"(a1), "r"(a2), "r"(a3), "r"(b0), "r"(b1));
}
__device__ __forceinline__ void mbar_init(uint32_t a, uint32_t c) {
    asm volatile("mbarrier.init.shared.b64 [%0], %1;" :: "r"(a), "r"(c) : "memory");
}
__device__ __forceinline__ void mbar_wait(uint32_t a, uint32_t par) {
    asm volatile(
        "{\n\t.reg .pred P1;\n\t"
        "W_%=:\n\t"
        "mbarrier.try_wait.parity.acquire.cta.shared::cta.b64 P1, [%0], %1, 0x989680;\n\t"
        "@P1 bra.uni D_%=;\n\t"
        "bra.uni W_%=;\n\t"
        "D_%=:\n\t}"
        :: "r"(a), "r"(par) : "memory");
}
__device__ __forceinline__ void mbar_arrive(uint32_t a) {
    asm volatile("mbarrier.arrive.shared.b64 _, [%0];" :: "r"(a) : "memory");
}

// fp16 tile: 64 rows x 256B, 16 chunks(16B)/row, chunk swizzle c ^= (row&7)
__device__ __forceinline__ uint32_t tile_addr(uint32_t base, uint32_t row, uint32_t chunk) {
    return base + row * 256u + ((chunk ^ (row & 7u)) << 4);
}

static constexpr int TILE_BYTES   = 16384;               // 64 B-rows x 256B
static constexpr int SMEM_BAR_OFF = NSTG * TILE_BYTES;   // 4 stages = 64KB
static constexpr int SMEM_DYN     = SMEM_BAR_OFF + 128;

// item idx in [0,16384): r = idx>>8 (A row-tile), mat = (idx>>7)&1, tj = idx&127

// ---------------- kernel A: normalize + diagonals + adversarial + zeroing ----
__global__ void __launch_bounds__(256) prep_kernel(const float* __restrict__ z1,
                                                   const float* __restrict__ z2,
                                                   const float* __restrict__ cpre,
                                                   const float* __restrict__ lab) {
    int gtid = blockIdx.x * 256 + threadIdx.x;
    if (gtid < 2 * NROWS) ((float*)g_rowsum)[gtid] = 0.f;

    int w = threadIdx.x >> 5, lane = threadIdx.x & 31;
    int row = blockIdx.x * 8 + w;
    float4 a = ((const float4*)(z1 + (size_t)row * NDIM))[lane];
    float4 b = ((const float4*)(z2 + (size_t)row * NDIM))[lane];
    float ss1 = warp_sum(a.x * a.x + a.y * a.y + a.z * a.z + a.w * a.w);
    float ss2 = warp_sum(b.x * b.x + b.y * b.y + b.z * b.z + b.w * b.w);
    float inv1 = 1.f / fmaxf(sqrtf(ss1), 1e-8f);
    float inv2 = 1.f / fmaxf(sqrtf(ss2), 1e-8f);
    float4 n1 = make_float4(a.x * inv1, a.y * inv1, a.z * inv1, a.w * inv1);
    float4 n2 = make_float4(b.x * inv2, b.y * inv2, b.z * inv2, b.w * inv2);
    float d12 = warp_sum(n1.x * n2.x + n1.y * n2.y + n1.z * n2.z + n1.w * n2.w);
    float d11 = warp_sum(n1.x * n1.x + n1.y * n1.y + n1.z * n1.z + n1.w * n1.w);

    __half2* pa = (__half2*)(g_a + (size_t)row * NDIM) + lane * 2;
    pa[0] = __floats2half2_rn(n1.x * EXP_SCALE, n1.y * EXP_SCALE);
    pa[1] = __floats2half2_rn(n1.z * EXP_SCALE, n1.w * EXP_SCALE);
    __half2* p1 = (__half2*)(g_b1 + (size_t)row * NDIM) + lane * 2;
    p1[0] = __floats2half2_rn(n1.x, n1.y);
    p1[1] = __floats2half2_rn(n1.z, n1.w);
    __half2* p2 = (__half2*)(g_b2 + (size_t)row * NDIM) + lane * 2;
    p2[0] = __floats2half2_rn(n2.x, n2.y);
    p2[1] = __floats2half2_rn(n2.z, n2.w);
    if (lane == 0) { g_d12[row] = d12; g_d11[row] = d11; }

    float2 cc = ((const float2*)(cpre + (size_t)row * NS))[lane];
    float2 ll = ((const float2*)(lab + (size_t)row * NS))[lane];
    float csum = warp_sum(cc.x * cc.x + cc.y * cc.y);
    float bv = ll.x; int bi = lane * 2; float bc = cc.x;
    if (ll.y > bv) { bv = ll.y; bi = lane * 2 + 1; bc = cc.y; }
#pragma unroll
    for (int o = 16; o > 0; o >>= 1) {
        float ov = __shfl_xor_sync(0xFFFFFFFFu, bv, o);
        int   oi = __shfl_xor_sync(0xFFFFFFFFu, bi, o);
        float oc = __shfl_xor_sync(0xFFFFFFFFu, bc, o);
        if (ov > bv || (ov == bv && oi < bi)) { bv = ov; bi = oi; bc = oc; }
    }
    if (lane == 0) {
        float picked = bc / fmaxf(sqrtf(csum), 1e-12f);
        g_adv[row] = -logf(1e-12f + 1.f - picked);
    }
}

// ---------------- kernel B: 2-CTA/SM warp-specialized sim + exp sums ----------
// 296 CTAs x 160 threads (4 consumer warps m32xn64 + 1 producer warp).
// fp16-accumulator mma (2x HMMA rate); epilogue feeds packed accumulators
// directly to ex2.approx.f16x2.
__global__ void __launch_bounds__(160, 2) sim_rowsum_kernel() {
    extern __shared__ char smem_raw[];
    const uint32_t base = smem_u32(smem_raw);
    const int tid = threadIdx.x, wid = tid >> 5, lane = tid & 31;
    const int k0 = (int)(((long long)blockIdx.x * TOTAL_ITEMS) / NCTA);
    const int k1 = (int)(((long long)(blockIdx.x + 1) * TOTAL_ITEMS) / NCTA);
    const int n_items = k1 - k0;

    if (tid == 0) {
#pragma unroll
        for (int s = 0; s < NSTG; ++s) {
            mbar_init(base + SMEM_BAR_OFF + s * 16, 32);      // full: 32 producer threads
            mbar_init(base + SMEM_BAR_OFF + s * 16 + 8, 4);   // empty: 4 consumer warps
        }
    }
    __syncthreads();

    if (wid == 4) {
        // ---------------- producer: stream 128x64 B tiles ----------------
        int s = 0, w = 0;
        for (int k = 0; k < n_items; ++k) {
            const int idx = k0 + k;
            const int mt = (idx >> 7) & 1, tj = idx & 127;
            mbar_wait(base + SMEM_BAR_OFF + s * 16 + 8, 1u ^ (uint32_t)(w & 1));
            const char* src = (const char*)((mt ? g_b1 : g_b2) + (size_t)tj * 64 * NDIM);
            const uint32_t stg = base + (uint32_t)s * TILE_BYTES;
#pragma unroll
            for (int jj = 0; jj < 32; ++jj) {
                uint32_t q = (uint32_t)lane + 32u * jj;   // 1024 16B chunks
                uint32_t r = q >> 4, c = q & 15u;
                uint32_t d = tile_addr(stg, r, c);
                asm volatile("cp.async.cg.shared.global [%0], [%1], 16;"
                             :: "r"(d), "l"(src + ((size_t)r << 8) + ((size_t)c << 4)) : "memory");
            }
            asm volatile("cp.async.mbarrier.arrive.noinc.shared::cta.b64 [%0];"
                         :: "r"(base + SMEM_BAR_OFF + s * 16) : "memory");
            if (++s == NSTG) { s = 0; w ^= 1; }
        }
        return;
    }

    // ---------------- consumers: 4 warps, m-slab 32 x n 64 each ----------------
    const int m_base = wid * 32;
    const uint32_t rB0 = (uint32_t)((lane & 7) + ((lane >> 4) << 3));
    const uint32_t gB  = (uint32_t)((lane >> 3) & 1);

    uint32_t af[2][8][4];
    float s00 = 0.f, s01 = 0.f, s10 = 0.f, s11 = 0.f;
    int akey = -1, ar = -1;
    int s = 0, w = 0;

    for (int k = 0; k < n_items; ++k) {
        const int idx = k0 + k;
        const int r = idx >> 8, mt = (idx >> 7) & 1;
        mbar_wait(base + SMEM_BAR_OFF + s * 16, (uint32_t)(w & 1));

        const int key = (r << 1) | mt;
        if (key != akey) {
            // flush accumulated row sums of the previous (row, mat) run
            if (akey >= 0) {
                float t0 = s00, t1 = s01, t2 = s10, t3 = s11;
#pragma unroll
                for (int o = 1; o <= 2; o <<= 1) {
                    t0 += __shfl_xor_sync(0xFFFFFFFFu, t0, o);
                    t1 += __shfl_xor_sync(0xFFFFFFFFu, t1, o);
                    t2 += __shfl_xor_sync(0xFFFFFFFFu, t2, o);
                    t3 += __shfl_xor_sync(0xFFFFFFFFu, t3, o);
                }
                if ((lane & 3) == 0) {
                    float* dst = &g_rowsum[akey & 1][(akey >> 1) * 128 + m_base + (lane >> 2)];
                    atomicAdd(dst,      t0);
                    atomicAdd(dst + 8,  t1);
                    atomicAdd(dst + 16, t2);
                    atomicAdd(dst + 24, t3);
                }
                s00 = s01 = s10 = s11 = 0.f;
            }
            if (r != ar) {
                // load A fragments from global (mma fragment layout, R12-validated;
                // byte layout identical for fp16)
                const char* Ab = (const char*)(g_a + (size_t)r * 128 * NDIM);
                const uint32_t R = (uint32_t)(m_base + (lane >> 2));
                const uint32_t c0 = (uint32_t)((lane & 3) * 2);
#pragma unroll
                for (int mb = 0; mb < 2; ++mb)
#pragma unroll
                    for (int kk = 0; kk < 8; ++kk) {
                        const char* p = Ab + (size_t)(R + mb * 16u) * 256 + kk * 32 + c0 * 2;
                        af[mb][kk][0] = *(const uint32_t*)p;
                        af[mb][kk][1] = *(const uint32_t*)(p + 8 * 256);
                        af[mb][kk][2] = *(const uint32_t*)(p + 16);
                        af[mb][kk][3] = *(const uint32_t*)(p + 8 * 256 + 16);
                    }
                ar = r;
            }
            akey = key;
        }

        const uint32_t bstage = base + (uint32_t)s * TILE_BYTES;
        uint32_t c[2][8][2];
#pragma unroll
        for (int mb = 0; mb < 2; ++mb)
#pragma unroll
            for (int n = 0; n < 8; ++n) { c[mb][n][0] = 0u; c[mb][n][1] = 0u; }

#pragma unroll
        for (int kk = 0; kk < 8; ++kk) {
            uint32_t bf[4][4];
#pragma unroll
            for (int nb = 0; nb < 4; ++nb) {
                uint32_t addr = tile_addr(bstage, rB0 + nb * 16u, 2u * kk + gB);
                ldsm_x4(bf[nb][0], bf[nb][1], bf[nb][2], bf[nb][3], addr);
            }
#pragma unroll
            for (int mb = 0; mb < 2; ++mb)
#pragma unroll
                for (int nb = 0; nb < 4; ++nb) {
                    mma_f16(c[mb][nb * 2][0], c[mb][nb * 2][1],
                            af[mb][kk][0], af[mb][kk][1], af[mb][kk][2], af[mb][kk][3],
                            bf[nb][0], bf[nb][1]);
                    mma_f16(c[mb][nb * 2 + 1][0], c[mb][nb * 2 + 1][1],
                            af[mb][kk][0], af[mb][kk][1], af[mb][kk][2], af[mb][kk][3],
                            bf[nb][2], bf[nb][3]);
                }
        }
        __syncwarp();
        if (lane == 0) mbar_arrive(base + SMEM_BAR_OFF + s * 16 + 8);

        // epilogue: ex2.approx.f16x2 directly on packed accumulators
#pragma unroll
        for (int n = 0; n < 8; ++n) {
            exp2h_acc(s00, c[0][n][0]);   // rows m_base + lane/4
            exp2h_acc(s01, c[0][n][1]);   // rows m_base + lane/4 + 8
            exp2h_acc(s10, c[1][n][0]);   // + 16
            exp2h_acc(s11, c[1][n][1]);   // + 24
        }
        if (++s == NSTG) { s = 0; w ^= 1; }
    }

    // final flush
    if (akey >= 0) {
#pragma unroll
        for (int o = 1; o <= 2; o <<= 1) {
            s00 += __shfl_xor_sync(0xFFFFFFFFu, s00, o);
            s01 += __shfl_xor_sync(0xFFFFFFFFu, s01, o);
            s10 += __shfl_xor_sync(0xFFFFFFFFu, s10, o);
            s11 += __shfl_xor_sync(0xFFFFFFFFu, s11, o);
        }
        if ((lane & 3) == 0) {
            float* dst = &g_rowsum[akey & 1][(akey >> 1) * 128 + m_base + (lane >> 2)];
            atomicAdd(dst,      s00);
            atomicAdd(dst + 8,  s01);
            atomicAdd(dst + 16, s10);
            atomicAdd(dst + 24, s11);
        }
    }
}

// ---------------- kernel C: final reduction ----------------
__global__ void __launch_bounds__(256) finish_kernel(float* __restrict__ out) {
    __shared__ float sc[256], sa[256];
    int tid = threadIdx.x;
    float c = 0.f, a = 0.f;
    for (int r = tid; r < NROWS; r += 256) {
        float num  = ex2f(EXP_SCALE * g_d12[r]);
        float diag = ex2f(EXP_SCALE * g_d11[r]);
        float den  = g_rowsum[0][r] + g_rowsum[1][r] - diag;
        c -= logf(1e-12f + num / den);
        a += g_adv[r];
    }
    sc[tid] = c; sa[tid] = a;
    __syncthreads();
    for (int st = 128; st > 0; st >>= 1) {
        if (tid < st) { sc[tid] += sc[tid + st]; sa[tid] += sa[tid + st]; }
        __syncthreads();
    }
    if (tid == 0)
        out[0] = sc[0] / (8192.0f * 16383.0f) + sa[0];
}

extern "C" void kernel_launch(void* const* d_in, const int* in_sizes, int n_in,
                              void* d_out, int out_size) {
    const float* z1  = (const float*)d_in[0];
    const float* z2  = (const float*)d_in[1];
    const float* c   = (const float*)d_in[2];
    const float* lab = (const float*)d_in[3];
    cudaFuncSetAttribute(sim_rowsum_kernel,
                         cudaFuncAttributeMaxDynamicSharedMemorySize, SMEM_DYN);
    prep_kernel<<<NROWS / 8, 256>>>(z1, z2, c, lab);
    sim_rowsum_kernel<<<NCTA, 160, SMEM_DYN>>>();
    finish_kernel<<<1, 256>>>((float*)d_out);
}

// round 17
// speedup vs baseline: 1.5776x; 1.1087x over previous
#include <cuda_runtime.h>
#include <cuda_fp16.h>
#include <cstdint>

#define NROWS 8192
#define NDIM  128
#define NS    64

static constexpr float EXP_SCALE = 14.4269504088896340736f; // log2(e)/tau
static constexpr int TOTAL_ITEMS = 16384;  // 64 rows x 2 mats x 128 col-tiles(64)
static constexpr int NCTA = 296;           // 2 CTAs per SM
static constexpr int NSTG = 4;

// ---------------- device scratch (fp16 operands) ----------------
__device__ __align__(256) __half g_a [NROWS * NDIM];  // n1 * log2(e)/tau
__device__ __align__(256) __half g_b1[NROWS * NDIM];  // n1
__device__ __align__(256) __half g_b2[NROWS * NDIM];  // n2
__device__ float g_d12[NROWS];
__device__ float g_d11[NROWS];
__device__ float g_adv[NROWS];
__device__ float g_rowsum[2][NROWS];

// ---------------- helpers ----------------
__device__ __forceinline__ uint32_t smem_u32(const void* p) {
    uint32_t a;
    asm("{ .reg .u64 t; cvta.to.shared.u64 t, %1; cvt.u32.u64 %0, t; }" : "=r"(a) : "l"(p));
    return a;
}
__device__ __forceinline__ float warp_sum(float v) {
#pragma unroll
    for (int o = 16; o > 0; o >>= 1) v += __shfl_xor_sync(0xFFFFFFFFu, v, o);
    return v;
}
__device__ __forceinline__ float ex2f(float x) {
    float y; asm("ex2.approx.f32 %0, %1;" : "=f"(y) : "f"(x)); return y;
}
// exp2 of both halves of a packed f16x2, accumulate into fp32 s
__device__ __forceinline__ void exp2h_acc(float& s, uint32_t h) {
    uint32_t e;
    asm("ex2.approx.f16x2 %0, %1;" : "=r"(e) : "r"(h));
    float fx, fy;
    asm("{.reg .b16 l,u; mov.b32 {l,u}, %2; cvt.f32.f16 %0, l; cvt.f32.f16 %1, u;}"
        : "=f"(fx), "=f"(fy) : "r"(e));
    s += fx + fy;
}
__device__ __forceinline__ void ldsm_x4(uint32_t& r0, uint32_t& r1, uint32_t& r2, uint32_t& r3,
                                        uint32_t addr) {
    asm volatile("ldmatrix.sync.aligned.m8n8.x4.shared.b16 {%0,%1,%2,%3}, [%4];"
                 : "=r"(r0), "=r"(r1), "=r"(r2), "=r"(r3) : "r"(addr));
}
// fp16-accumulator mma: D(f16x2 x2) = A(f16) * B(f16) + D
__device__ __forceinline__ void mma_f16(uint32_t& c0, uint32_t& c1,
                                        uint32_t a0, uint32_t a1, uint32_t a2, uint32_t a3,
                                        uint32_t b0, uint32_t b1) {
    asm volatile(
        "mma.sync.aligned.m16n8k16.row.col.f16.f16.f16.f16 "
        "{%0,%1},{%2,%3,%4,%5},{%6,%7},{%0,%1};"
        : "+r"(c0), "+r"(c1)
        : "r"(a0), "r"(a1), "r"(a2), "r"(a3), "r"(b0), "r"(b1));
}
__device__ __forceinline__ void mbar_init(uint32_t a, uint32_t c) {
    asm volatile("mbarrier.init.shared.b64 [%0], %1;" :: "r"(a), "r"(c) : "memory");
}
__device__ __forceinline__ void mbar_wait(uint32_t a, uint32_t par) {
    asm volatile(
        "{\n\t.reg .pred P1;\n\t"
        "W_%=:\n\t"
        "mbarrier.try_wait.parity.acquire.cta.shared::cta.b64 P1, [%0], %1, 0x989680;\n\t"
        "@P1 bra.uni D_%=;\n\t"
        "bra.uni W_%=;\n\t"
        "D_%=:\n\t}"
        :: "r"(a), "r"(par) : "memory");
}
__device__ __forceinline__ void mbar_arrive(uint32_t a) {
    asm volatile("mbarrier.arrive.shared.b64 _, [%0];" :: "r"(a) : "memory");
}

// fp16 tile: 64 rows x 256B, 16 chunks(16B)/row, chunk swizzle c ^= (row&7)
__device__ __forceinline__ uint32_t tile_addr(uint32_t base, uint32_t row, uint32_t chunk) {
    return base + row * 256u + ((chunk ^ (row & 7u)) << 4);
}

static constexpr int TILE_BYTES   = 16384;               // 64 B-rows x 256B
static constexpr int SMEM_BAR_OFF = NSTG * TILE_BYTES;   // 4 stages = 64KB
static constexpr int SMEM_DYN     = SMEM_BAR_OFF + 128;

// item idx in [0,16384): r = idx>>8 (A row-tile), mat = (idx>>7)&1, tj = idx&127

// ---------------- kernel A: normalize + diagonals + adversarial + zeroing ----
// 512 blocks x 256 threads; each warp handles TWO rows for doubled MLP and
// ILP'd shuffle-reduction chains.
__global__ void __launch_bounds__(256) prep_kernel(const float* __restrict__ z1,
                                                   const float* __restrict__ z2,
                                                   const float* __restrict__ cpre,
                                                   const float* __restrict__ lab) {
    int gtid = blockIdx.x * 256 + threadIdx.x;
    if (gtid < 2 * NROWS) ((float*)g_rowsum)[gtid] = 0.f;

    int w = threadIdx.x >> 5, lane = threadIdx.x & 31;
    int row0 = blockIdx.x * 16 + w * 2;
    int row1 = row0 + 1;

    float4 a0 = ((const float4*)(z1 + (size_t)row0 * NDIM))[lane];
    float4 a1 = ((const float4*)(z1 + (size_t)row1 * NDIM))[lane];
    float4 b0 = ((const float4*)(z2 + (size_t)row0 * NDIM))[lane];
    float4 b1 = ((const float4*)(z2 + (size_t)row1 * NDIM))[lane];
    float2 cc0 = ((const float2*)(cpre + (size_t)row0 * NS))[lane];
    float2 cc1 = ((const float2*)(cpre + (size_t)row1 * NS))[lane];
    float2 ll0 = ((const float2*)(lab + (size_t)row0 * NS))[lane];
    float2 ll1 = ((const float2*)(lab + (size_t)row1 * NS))[lane];

    // 4 independent reduction chains (ILP)
    float ss1a = a0.x*a0.x + a0.y*a0.y + a0.z*a0.z + a0.w*a0.w;
    float ss1b = a1.x*a1.x + a1.y*a1.y + a1.z*a1.z + a1.w*a1.w;
    float ss2a = b0.x*b0.x + b0.y*b0.y + b0.z*b0.z + b0.w*b0.w;
    float ss2b = b1.x*b1.x + b1.y*b1.y + b1.z*b1.z + b1.w*b1.w;
#pragma unroll
    for (int o = 16; o > 0; o >>= 1) {
        ss1a += __shfl_xor_sync(0xFFFFFFFFu, ss1a, o);
        ss1b += __shfl_xor_sync(0xFFFFFFFFu, ss1b, o);
        ss2a += __shfl_xor_sync(0xFFFFFFFFu, ss2a, o);
        ss2b += __shfl_xor_sync(0xFFFFFFFFu, ss2b, o);
    }
    float i1a = 1.f / fmaxf(sqrtf(ss1a), 1e-8f);
    float i1b = 1.f / fmaxf(sqrtf(ss1b), 1e-8f);
    float i2a = 1.f / fmaxf(sqrtf(ss2a), 1e-8f);
    float i2b = 1.f / fmaxf(sqrtf(ss2b), 1e-8f);
    float4 n1a = make_float4(a0.x*i1a, a0.y*i1a, a0.z*i1a, a0.w*i1a);
    float4 n1b = make_float4(a1.x*i1b, a1.y*i1b, a1.z*i1b, a1.w*i1b);
    float4 n2a = make_float4(b0.x*i2a, b0.y*i2a, b0.z*i2a, b0.w*i2a);
    float4 n2b = make_float4(b1.x*i2b, b1.y*i2b, b1.z*i2b, b1.w*i2b);

    float d12a = n1a.x*n2a.x + n1a.y*n2a.y + n1a.z*n2a.z + n1a.w*n2a.w;
    float d12b = n1b.x*n2b.x + n1b.y*n2b.y + n1b.z*n2b.z + n1b.w*n2b.w;
    float d11a = n1a.x*n1a.x + n1a.y*n1a.y + n1a.z*n1a.z + n1a.w*n1a.w;
    float d11b = n1b.x*n1b.x + n1b.y*n1b.y + n1b.z*n1b.z + n1b.w*n1b.w;
    float csa  = cc0.x*cc0.x + cc0.y*cc0.y;
    float csb  = cc1.x*cc1.x + cc1.y*cc1.y;
#pragma unroll
    for (int o = 16; o > 0; o >>= 1) {
        d12a += __shfl_xor_sync(0xFFFFFFFFu, d12a, o);
        d12b += __shfl_xor_sync(0xFFFFFFFFu, d12b, o);
        d11a += __shfl_xor_sync(0xFFFFFFFFu, d11a, o);
        d11b += __shfl_xor_sync(0xFFFFFFFFu, d11b, o);
        csa  += __shfl_xor_sync(0xFFFFFFFFu, csa, o);
        csb  += __shfl_xor_sync(0xFFFFFFFFu, csb, o);
    }

    __half2* pa0 = (__half2*)(g_a + (size_t)row0 * NDIM) + lane * 2;
    pa0[0] = __floats2half2_rn(n1a.x * EXP_SCALE, n1a.y * EXP_SCALE);
    pa0[1] = __floats2half2_rn(n1a.z * EXP_SCALE, n1a.w * EXP_SCALE);
    __half2* pa1 = (__half2*)(g_a + (size_t)row1 * NDIM) + lane * 2;
    pa1[0] = __floats2half2_rn(n1b.x * EXP_SCALE, n1b.y * EXP_SCALE);
    pa1[1] = __floats2half2_rn(n1b.z * EXP_SCALE, n1b.w * EXP_SCALE);
    __half2* p10 = (__half2*)(g_b1 + (size_t)row0 * NDIM) + lane * 2;
    p10[0] = __floats2half2_rn(n1a.x, n1a.y);
    p10[1] = __floats2half2_rn(n1a.z, n1a.w);
    __half2* p11 = (__half2*)(g_b1 + (size_t)row1 * NDIM) + lane * 2;
    p11[0] = __floats2half2_rn(n1b.x, n1b.y);
    p11[1] = __floats2half2_rn(n1b.z, n1b.w);
    __half2* p20 = (__half2*)(g_b2 + (size_t)row0 * NDIM) + lane * 2;
    p20[0] = __floats2half2_rn(n2a.x, n2a.y);
    p20[1] = __floats2half2_rn(n2a.z, n2a.w);
    __half2* p21 = (__half2*)(g_b2 + (size_t)row1 * NDIM) + lane * 2;
    p21[0] = __floats2half2_rn(n2b.x, n2b.y);
    p21[1] = __floats2half2_rn(n2b.z, n2b.w);
    if (lane == 0) {
        g_d12[row0] = d12a; g_d12[row1] = d12b;
        g_d11[row0] = d11a; g_d11[row1] = d11b;
    }

    // adversarial argmax, rows 0 and 1 interleaved (first-max tie-break)
    float bva = ll0.x; int bia = lane * 2; float bca = cc0.x;
    if (ll0.y > bva) { bva = ll0.y; bia = lane * 2 + 1; bca = cc0.y; }
    float bvb = ll1.x; int bib = lane * 2; float bcb = cc1.x;
    if (ll1.y > bvb) { bvb = ll1.y; bib = lane * 2 + 1; bcb = cc1.y; }
#pragma unroll
    for (int o = 16; o > 0; o >>= 1) {
        float ova = __shfl_xor_sync(0xFFFFFFFFu, bva, o);
        int   oia = __shfl_xor_sync(0xFFFFFFFFu, bia, o);
        float oca = __shfl_xor_sync(0xFFFFFFFFu, bca, o);
        float ovb = __shfl_xor_sync(0xFFFFFFFFu, bvb, o);
        int   oib = __shfl_xor_sync(0xFFFFFFFFu, bib, o);
        float ocb = __shfl_xor_sync(0xFFFFFFFFu, bcb, o);
        if (ova > bva || (ova == bva && oia < bia)) { bva = ova; bia = oia; bca = oca; }
        if (ovb > bvb || (ovb == bvb && oib < bib)) { bvb = ovb; bib = oib; bcb = ocb; }
    }
    if (lane == 0) {
        g_adv[row0] = -logf(1e-12f + 1.f - bca / fmaxf(sqrtf(csa), 1e-12f));
        g_adv[row1] = -logf(1e-12f + 1.f - bcb / fmaxf(sqrtf(csb), 1e-12f));
    }
}

// ---------------- kernel B: 2-CTA/SM warp-specialized sim + exp sums ----------
// (byte-identical to R16 — 104.5us baseline, rel_err 0.0)
__global__ void __launch_bounds__(160, 2) sim_rowsum_kernel() {
    extern __shared__ char smem_raw[];
    const uint32_t base = smem_u32(smem_raw);
    const int tid = threadIdx.x, wid = tid >> 5, lane = tid & 31;
    const int k0 = (int)(((long long)blockIdx.x * TOTAL_ITEMS) / NCTA);
    const int k1 = (int)(((long long)(blockIdx.x + 1) * TOTAL_ITEMS) / NCTA);
    const int n_items = k1 - k0;

    if (tid == 0) {
#pragma unroll
        for (int s = 0; s < NSTG; ++s) {
            mbar_init(base + SMEM_BAR_OFF + s * 16, 32);      // full: 32 producer threads
            mbar_init(base + SMEM_BAR_OFF + s * 16 + 8, 4);   // empty: 4 consumer warps
        }
    }
    __syncthreads();

    if (wid == 4) {
        // ---------------- producer: stream 128x64 B tiles ----------------
        int s = 0, w = 0;
        for (int k = 0; k < n_items; ++k) {
            const int idx = k0 + k;
            const int mt = (idx >> 7) & 1, tj = idx & 127;
            mbar_wait(base + SMEM_BAR_OFF + s * 16 + 8, 1u ^ (uint32_t)(w & 1));
            const char* src = (const char*)((mt ? g_b1 : g_b2) + (size_t)tj * 64 * NDIM);
            const uint32_t stg = base + (uint32_t)s * TILE_BYTES;
#pragma unroll
            for (int jj = 0; jj < 32; ++jj) {
                uint32_t q = (uint32_t)lane + 32u * jj;   // 1024 16B chunks
                uint32_t r = q >> 4, c = q & 15u;
                uint32_t d = tile_addr(stg, r, c);
                asm volatile("cp.async.cg.shared.global [%0], [%1], 16;"
                             :: "r"(d), "l"(src + ((size_t)r << 8) + ((size_t)c << 4)) : "memory");
            }
            asm volatile("cp.async.mbarrier.arrive.noinc.shared::cta.b64 [%0];"
                         :: "r"(base + SMEM_BAR_OFF + s * 16) : "memory");
            if (++s == NSTG) { s = 0; w ^= 1; }
        }
        return;
    }

    // ---------------- consumers: 4 warps, m-slab 32 x n 64 each ----------------
    const int m_base = wid * 32;
    const uint32_t rB0 = (uint32_t)((lane & 7) + ((lane >> 4) << 3));
    const uint32_t gB  = (uint32_t)((lane >> 3) & 1);

    uint32_t af[2][8][4];
    float s00 = 0.f, s01 = 0.f, s10 = 0.f, s11 = 0.f;
    int akey = -1, ar = -1;
    int s = 0, w = 0;

    for (int k = 0; k < n_items; ++k) {
        const int idx = k0 + k;
        const int r = idx >> 8, mt = (idx >> 7) & 1;
        mbar_wait(base + SMEM_BAR_OFF + s * 16, (uint32_t)(w & 1));

        const int key = (r << 1) | mt;
        if (key != akey) {
            if (akey >= 0) {
                float t0 = s00, t1 = s01, t2 = s10, t3 = s11;
#pragma unroll
                for (int o = 1; o <= 2; o <<= 1) {
                    t0 += __shfl_xor_sync(0xFFFFFFFFu, t0, o);
                    t1 += __shfl_xor_sync(0xFFFFFFFFu, t1, o);
                    t2 += __shfl_xor_sync(0xFFFFFFFFu, t2, o);
                    t3 += __shfl_xor_sync(0xFFFFFFFFu, t3, o);
                }
                if ((lane & 3) == 0) {
                    float* dst = &g_rowsum[akey & 1][(akey >> 1) * 128 + m_base + (lane >> 2)];
                    atomicAdd(dst,      t0);
                    atomicAdd(dst + 8,  t1);
                    atomicAdd(dst + 16, t2);
                    atomicAdd(dst + 24, t3);
                }
                s00 = s01 = s10 = s11 = 0.f;
            }
            if (r != ar) {
                const char* Ab = (const char*)(g_a + (size_t)r * 128 * NDIM);
                const uint32_t R = (uint32_t)(m_base + (lane >> 2));
                const uint32_t c0 = (uint32_t)((lane & 3) * 2);
#pragma unroll
                for (int mb = 0; mb < 2; ++mb)
#pragma unroll
                    for (int kk = 0; kk < 8; ++kk) {
                        const char* p = Ab + (size_t)(R + mb * 16u) * 256 + kk * 32 + c0 * 2;
                        af[mb][kk][0] = *(const uint32_t*)p;
                        af[mb][kk][1] = *(const uint32_t*)(p + 8 * 256);
                        af[mb][kk][2] = *(const uint32_t*)(p + 16);
                        af[mb][kk][3] = *(const uint32_t*)(p + 8 * 256 + 16);
                    }
                ar = r;
            }
            akey = key;
        }

        const uint32_t bstage = base + (uint32_t)s * TILE_BYTES;
        uint32_t c[2][8][2];
#pragma unroll
        for (int mb = 0; mb < 2; ++mb)
#pragma unroll
            for (int n = 0; n < 8; ++n) { c[mb][n][0] = 0u; c[mb][n][1] = 0u; }

#pragma unroll
        for (int kk = 0; kk < 8; ++kk) {
            uint32_t bf[4][4];
#pragma unroll
            for (int nb = 0; nb < 4; ++nb) {
                uint32_t addr = tile_addr(bstage, rB0 + nb * 16u, 2u * kk + gB);
                ldsm_x4(bf[nb][0], bf[nb][1], bf[nb][2], bf[nb][3], addr);
            }
#pragma unroll
            for (int mb = 0; mb < 2; ++mb)
#pragma unroll
                for (int nb = 0; nb < 4; ++nb) {
                    mma_f16(c[mb][nb * 2][0], c[mb][nb * 2][1],
                            af[mb][kk][0], af[mb][kk][1], af[mb][kk][2], af[mb][kk][3],
                            bf[nb][0], bf[nb][1]);
                    mma_f16(c[mb][nb * 2 + 1][0], c[mb][nb * 2 + 1][1],
                            af[mb][kk][0], af[mb][kk][1], af[mb][kk][2], af[mb][kk][3],
                            bf[nb][2], bf[nb][3]);
                }
        }
        __syncwarp();
        if (lane == 0) mbar_arrive(base + SMEM_BAR_OFF + s * 16 + 8);

#pragma unroll
        for (int n = 0; n < 8; ++n) {
            exp2h_acc(s00, c[0][n][0]);
            exp2h_acc(s01, c[0][n][1]);
            exp2h_acc(s10, c[1][n][0]);
            exp2h_acc(s11, c[1][n][1]);
        }
        if (++s == NSTG) { s = 0; w ^= 1; }
    }

    if (akey >= 0) {
#pragma unroll
        for (int o = 1; o <= 2; o <<= 1) {
            s00 += __shfl_xor_sync(0xFFFFFFFFu, s00, o);
            s01 += __shfl_xor_sync(0xFFFFFFFFu, s01, o);
            s10 += __shfl_xor_sync(0xFFFFFFFFu, s10, o);
            s11 += __shfl_xor_sync(0xFFFFFFFFu, s11, o);
        }
        if ((lane & 3) == 0) {
            float* dst = &g_rowsum[akey & 1][(akey >> 1) * 128 + m_base + (lane >> 2)];
            atomicAdd(dst,      s00);
            atomicAdd(dst + 8,  s01);
            atomicAdd(dst + 16, s10);
            atomicAdd(dst + 24, s11);
        }
    }
}

// ---------------- kernel C: final reduction (1024 threads) ----------------
__global__ void __launch_bounds__(1024) finish_kernel(float* __restrict__ out) {
    __shared__ float sc[1024], sa[1024];
    int tid = threadIdx.x;
    float c = 0.f, a = 0.f;
#pragma unroll
    for (int it = 0; it < NROWS / 1024; ++it) {
        int r = it * 1024 + tid;
        float num  = ex2f(EXP_SCALE * g_d12[r]);
        float diag = ex2f(EXP_SCALE * g_d11[r]);
        float den  = g_rowsum[0][r] + g_rowsum[1][r] - diag;
        c -= logf(1e-12f + num / den);
        a += g_adv[r];
    }
    sc[tid] = c; sa[tid] = a;
    __syncthreads();
    for (int st = 512; st > 0; st >>= 1) {
        if (tid < st) { sc[tid] += sc[tid + st]; sa[tid] += sa[tid + st]; }
        __syncthreads();
    }
    if (tid == 0)
        out[0] = sc[0] / (8192.0f * 16383.0f) + sa[0];
}

extern "C" void kernel_launch(void* const* d_in, const int* in_sizes, int n_in,
                              void* d_out, int out_size) {
    const float* z1  = (const float*)d_in[0];
    const float* z2  = (const float*)d_in[1];
    const float* c   = (const float*)d_in[2];
    const float* lab = (const float*)d_in[3];
    cudaFuncSetAttribute(sim_rowsum_kernel,
                         cudaFuncAttributeMaxDynamicSharedMemorySize, SMEM_DYN);
    prep_kernel<<<NROWS / 16, 256>>>(z1, z2, c, lab);
    sim_rowsum_kernel<<<NCTA, 160, SMEM_DYN>>>();
    finish_kernel<<<1, 1024>>>((float*)d_out);
}